// round 1
// baseline (speedup 1.0000x reference)
#include <cuda_runtime.h>
#include <cuda_bf16.h>
#include <math.h>

// Problem constants
#define BB    32
#define CC    12
#define HH_   64
#define WW_   64
#define HW_   4096
#define HID   128
#define CONDC 4
#define CIN1  16
#define OUTS  276          // 12 * 23
#define NB    8
#define TAILF 3.0f
#define MBWF  0.001f
#define MBHF  0.001f
#define MDF   0.001f
#define NTOT  (BB*CC*HW_)  // 1572864
#define PERB  (CC*HW_)     // 49152

// ---------------- scratch (no cudaMalloc allowed) ----------------
__device__ float g_netin[(size_t)BB*CIN1*HW_];     // 2.1M
__device__ float g_h1[(size_t)BB*HID*HW_];          // 16.8M
__device__ float g_h2[(size_t)BB*HID*HW_];          // 16.8M
__device__ float g_params[(size_t)BB*OUTS*HW_];     // 36.2M
__device__ float g_lad[(size_t)NTOT];               // 1.57M

// ---------------- concat x + conditioning ----------------
__global__ void concat_kernel(const float* __restrict__ x, const float* __restrict__ cond) {
    int i = blockIdx.x * blockDim.x + threadIdx.x;
    const int N = BB * CIN1 * HW_;
    if (i >= N) return;
    int hw = i & (HW_ - 1);
    int bc = i >> 12;
    int c = bc % CIN1;
    int b = bc / CIN1;
    float v;
    if (c < CC) v = x[((size_t)b*CC + c)*HW_ + hw];
    else        v = cond[((size_t)b*CONDC + (c - CC))*HW_ + hw];
    g_netin[i] = v;
}

// ---------------- implicit-GEMM conv (SAME, stride 1) ----------------
// One block: 64 output channels x one image row (64 pixels). 256 threads, 4x4 microtile.
template<int CIN, int KH, int KW, bool RELU>
__global__ __launch_bounds__(256)
void conv_gemm(const float* __restrict__ in, const float* __restrict__ wgt,
               const float* __restrict__ bias, float* __restrict__ out, int Cout)
{
    constexpr int K  = CIN * KH * KW;
    constexpr int BK = 16;
    constexpr int BM = 64;
    __shared__ float As[BK][BM + 1];
    __shared__ float Bs[BK][64];

    const int b  = blockIdx.z;
    const int h  = blockIdx.y;
    const int ocBase = blockIdx.x * BM;
    const int tid = threadIdx.x;
    const int tx = tid & 15;   // n dir
    const int ty = tid >> 4;   // m dir

    const float* inb = in + (size_t)b * CIN * HW_;

    float acc[4][4];
    #pragma unroll
    for (int i = 0; i < 4; ++i)
        #pragma unroll
        for (int j = 0; j < 4; ++j) acc[i][j] = 0.f;

    for (int k0 = 0; k0 < K; k0 += BK) {
        // load A tile (weights) : As[kk][m]
        #pragma unroll
        for (int p = 0; p < 4; ++p) {
            int idx = tid + p * 256;
            int kk = idx & 15;
            int m  = idx >> 4;
            int oc = ocBase + m;
            float v = 0.f;
            if (oc < Cout) v = wgt[(size_t)oc * K + k0 + kk];
            As[kk][m] = v;
        }
        // load B tile (input patches) : Bs[kr][n]
        #pragma unroll
        for (int p = 0; p < 4; ++p) {
            int idx = tid + p * 256;
            int n  = idx & 63;
            int kr = idx >> 6;
            int kk = k0 + kr;
            int ic, kh, kw;
            if (KH == 1 && KW == 1) { ic = kk; kh = 0; kw = 0; }
            else { ic = kk / (KH*KW); int r = kk - ic*(KH*KW); kh = r / KW; kw = r - kh*KW; }
            int hh = h + kh - (KH/2);
            int ww = n + kw - (KW/2);
            float v = 0.f;
            if (hh >= 0 && hh < HH_ && ww >= 0 && ww < WW_)
                v = inb[((size_t)ic * HH_ + hh) * WW_ + ww];
            Bs[kr][n] = v;
        }
        __syncthreads();
        #pragma unroll
        for (int kk = 0; kk < BK; ++kk) {
            float a[4], bb[4];
            #pragma unroll
            for (int i = 0; i < 4; ++i) a[i] = As[kk][ty*4 + i];
            #pragma unroll
            for (int j = 0; j < 4; ++j) bb[j] = Bs[kk][tx*4 + j];
            #pragma unroll
            for (int i = 0; i < 4; ++i)
                #pragma unroll
                for (int j = 0; j < 4; ++j)
                    acc[i][j] = fmaf(a[i], bb[j], acc[i][j]);
        }
        __syncthreads();
    }

    #pragma unroll
    for (int i = 0; i < 4; ++i) {
        int oc = ocBase + ty*4 + i;
        if (oc >= Cout) continue;
        float bv = bias[oc];
        float* op = out + (((size_t)b * Cout + oc) * HH_ + h) * WW_;
        #pragma unroll
        for (int j = 0; j < 4; ++j) {
            float v = acc[i][j] + bv;
            if (RELU) v = fmaxf(v, 0.f);
            op[tx*4 + j] = v;
        }
    }
}

// ---------------- RQS pointwise transform ----------------
__device__ __forceinline__ float softplusf(float v) {
    return (v > 20.f) ? v : log1pf(__expf(v) * 0.f + expf(v)); // keep accurate expf
}

__global__ void rqs_kernel(const float* __restrict__ x, float* __restrict__ y)
{
    int i = blockIdx.x * blockDim.x + threadIdx.x;
    if (i >= NTOT) return;
    int hw = i & (HW_ - 1);
    int bc = i >> 12;          // b*CC + c
    int c = bc % CC;
    int b = bc / CC;
    const float* pp = g_params + (((size_t)b * OUTS + c * 23) * HW_) + hw; // param j at pp[j*HW_]

    float xv = x[i];
    bool inside = (xv >= -TAILF) && (xv <= TAILF);
    float xin = fminf(fmaxf(xv, -TAILF), TAILF);

    // widths: softmax(uw) -> affine -> cumsum -> knots cw[0..8]
    float u[NB];
    float mx = -1e30f;
    #pragma unroll
    for (int j = 0; j < NB; ++j) { u[j] = pp[(size_t)j * HW_]; mx = fmaxf(mx, u[j]); }
    float se = 0.f;
    #pragma unroll
    for (int j = 0; j < NB; ++j) { u[j] = expf(u[j] - mx); se += u[j]; }
    float inv = 1.f / se;
    float cw[NB + 1];
    cw[0] = -TAILF;
    float cs = 0.f;
    #pragma unroll
    for (int k = 0; k < NB; ++k) {
        cs += MBWF + (1.f - MBWF * NB) * (u[k] * inv);
        cw[k + 1] = 2.f * TAILF * cs - TAILF;
    }
    cw[NB] = TAILF;

    // bin index
    int t = 0;
    #pragma unroll
    for (int k = 1; k < NB; ++k) t += (xin >= cw[k]) ? 1 : 0;
    float in_cw = cw[t];
    float in_w  = cw[t + 1] - cw[t];

    // heights
    mx = -1e30f;
    #pragma unroll
    for (int j = 0; j < NB; ++j) { u[j] = pp[(size_t)(NB + j) * HW_]; mx = fmaxf(mx, u[j]); }
    se = 0.f;
    #pragma unroll
    for (int j = 0; j < NB; ++j) { u[j] = expf(u[j] - mx); se += u[j]; }
    inv = 1.f / se;
    float ch[NB + 1];
    ch[0] = -TAILF;
    cs = 0.f;
    #pragma unroll
    for (int k = 0; k < NB; ++k) {
        cs += MBHF + (1.f - MBHF * NB) * (u[k] * inv);
        ch[k + 1] = 2.f * TAILF * cs - TAILF;
    }
    ch[NB] = TAILF;
    float in_ch = ch[t];
    float in_h  = ch[t + 1] - ch[t];

    // derivatives: only the two needed (boundary pad evaluates to exactly 1.0)
    float d0 = 1.0f, d1 = 1.0f;
    if (t > 0)      d0 = MDF + softplusf(pp[(size_t)(2*NB + t - 1) * HW_]);
    if (t < NB - 1) d1 = MDF + softplusf(pp[(size_t)(2*NB + t) * HW_]);

    float delta = in_h / in_w;
    float th  = (xin - in_cw) / in_w;
    float tom = th * (1.f - th);
    float numer = in_h * (delta * th * th + d0 * tom);
    float denom = delta + (d0 + d1 - 2.f * delta) * tom;
    float yv = in_ch + numer / denom;
    float omt = 1.f - th;
    float dnum = delta * delta * (d1 * th * th + 2.f * delta * tom + d0 * omt * omt);
    float lad = logf(dnum) - 2.f * logf(denom);

    y[i] = inside ? yv : xv;
    g_lad[i] = inside ? lad : 0.f;
}

// ---------------- deterministic per-batch logdet reduction ----------------
__global__ void logdet_reduce(const float* __restrict__ logdet, float* __restrict__ out)
{
    int b = blockIdx.x;
    const float* p = g_lad + (size_t)b * PERB;
    double s = 0.0;
    for (int i = threadIdx.x; i < PERB; i += 256) s += (double)p[i];
    __shared__ double sm[256];
    sm[threadIdx.x] = s;
    __syncthreads();
    for (int st = 128; st > 0; st >>= 1) {
        if (threadIdx.x < st) sm[threadIdx.x] += sm[threadIdx.x + st];
        __syncthreads();
    }
    if (threadIdx.x == 0) out[b] = logdet[b] + (float)sm[0];
}

// ---------------- launch ----------------
extern "C" void kernel_launch(void* const* d_in, const int* in_sizes, int n_in,
                              void* d_out, int out_size)
{
    const float* x    = (const float*)d_in[0];
    const float* ld   = (const float*)d_in[1];
    const float* cond = (const float*)d_in[2];
    const float* w1   = (const float*)d_in[3];
    const float* b1   = (const float*)d_in[4];
    const float* w2   = (const float*)d_in[5];
    const float* b2   = (const float*)d_in[6];
    const float* w3   = (const float*)d_in[7];
    const float* b3   = (const float*)d_in[8];
    float* out = (float*)d_out;

    float *p_netin, *p_h1, *p_h2, *p_params;
    cudaGetSymbolAddress((void**)&p_netin, g_netin);
    cudaGetSymbolAddress((void**)&p_h1, g_h1);
    cudaGetSymbolAddress((void**)&p_h2, g_h2);
    cudaGetSymbolAddress((void**)&p_params, g_params);

    {
        const int N = BB * CIN1 * HW_;
        concat_kernel<<<(N + 255) / 256, 256>>>(x, cond);
    }
    conv_gemm<CIN1, 3, 3, true ><<<dim3(2, HH_, BB), 256>>>(p_netin, w1, b1, p_h1, HID);
    conv_gemm<HID,  1, 1, true ><<<dim3(2, HH_, BB), 256>>>(p_h1,    w2, b2, p_h2, HID);
    conv_gemm<HID,  3, 3, false><<<dim3(5, HH_, BB), 256>>>(p_h2,    w3, b3, p_params, OUTS);
    rqs_kernel<<<(NTOT + 255) / 256, 256>>>(x, out);
    logdet_reduce<<<BB, 256>>>(ld, out + NTOT);
}

// round 3
// speedup vs baseline: 2.2925x; 2.2925x over previous
#include <cuda_runtime.h>
#include <cuda_bf16.h>
#include <math.h>
#include <cstdint>

// Problem constants
#define BB    32
#define CC    12
#define HH_   64
#define WW_   64
#define HW_   4096
#define HID   128
#define CONDC 4
#define CIN1  16
#define OUTS  276          // 12 * 23
#define NB    8
#define TAILF 3.0f
#define MBWF  0.001f
#define MBHF  0.001f
#define MDF   0.001f
#define NTOT  (BB*CC*HW_)  // 1572864
#define PERB  (CC*HW_)     // 49152

// ---------------- scratch (no cudaMalloc allowed) ----------------
__device__ float g_netin[(size_t)BB*CIN1*HW_];
__device__ float g_h1[(size_t)BB*HID*HW_];
__device__ float g_h2[(size_t)BB*HID*HW_];
__device__ float g_params[(size_t)BB*OUTS*HW_];
__device__ float g_lad[(size_t)NTOT];

// ---------------- helpers ----------------
__device__ __forceinline__ uint32_t cvt_tf32(float f) {
    uint32_t r;
    asm("cvt.rna.tf32.f32 %0, %1;" : "=r"(r) : "f"(f));
    return r;
}

__device__ __forceinline__ void mma_tf32(float c[4],
                                         uint32_t a0, uint32_t a1, uint32_t a2, uint32_t a3,
                                         uint32_t b0, uint32_t b1) {
    asm volatile(
        "mma.sync.aligned.m16n8k8.row.col.f32.tf32.tf32.f32 "
        "{%0,%1,%2,%3}, {%4,%5,%6,%7}, {%8,%9}, {%0,%1,%2,%3};"
        : "+f"(c[0]), "+f"(c[1]), "+f"(c[2]), "+f"(c[3])
        : "r"(a0), "r"(a1), "r"(a2), "r"(a3), "r"(b0), "r"(b1));
}

// ---------------- concat x + conditioning ----------------
__global__ void concat_kernel(const float* __restrict__ x, const float* __restrict__ cond) {
    int i = blockIdx.x * blockDim.x + threadIdx.x;
    const int N = BB * CIN1 * HW_;
    if (i >= N) return;
    int hw = i & (HW_ - 1);
    int bc = i >> 12;
    int c = bc % CIN1;
    int b = bc / CIN1;
    float v;
    if (c < CC) v = x[((size_t)b*CC + c)*HW_ + hw];
    else        v = cond[((size_t)b*CONDC + (c - CC))*HW_ + hw];
    g_netin[i] = v;
}

// ---------------- tf32 mma.sync implicit-GEMM conv ----------------
// CTA: 256 threads (8 warps, 2(M) x 4(N)), tile M=128 oc x N=256 pixels, BK=32.
// Warp tile 64x64 (4 m16 tiles x 8 n8 tiles, acc 128 regs).
// SMEM per stage: A[m 0..127][k 0..31] swizzled (k ^ ((m&3)<<3)), 16KB;
//                 B[n 0..255][p(k) interleaved] swizzled (p ^ ((n&3)<<3)), 32KB.
// Double-buffered with register-prefetch of the next chunk.
#define STAGE_WORDS (48 * 1024 / 4)
#define A_WORDS     (128 * 32)

template<int KH, bool RELU, int COUT, int KTOT>
__global__ __launch_bounds__(256, 1)
void conv_mma(const float* __restrict__ in, const float* __restrict__ wgt,
              const float* __restrict__ bias, float* __restrict__ out)
{
    constexpr int NC = (KTOT + 31) / 32;
    constexpr int CIN = KTOT / (KH * KH);
    extern __shared__ float smemf[];

    const int tid  = threadIdx.x;
    const int wid  = tid >> 5;
    const int lane = tid & 31;
    const int g    = lane >> 2;   // 0..7
    const int tq   = lane & 3;    // 0..3
    const int wm   = (wid & 1) * 64;
    const int wn   = (wid >> 1) * 64;

    const int b     = blockIdx.z;
    const int mbase = blockIdx.y * 128;
    const int h0    = blockIdx.x * 4;         // 4 image rows = 256 pixels
    const int pix0  = blockIdx.x * 256;

    const float* inb = in + (size_t)b * CIN * HW_;

    // A-loader map: oc = mbase + p*32 + (tid>>3), kq = tid&7 (k-run 4*kq)
    const int a_ocl = tid >> 3;   // 0..31
    const int a_kq  = tid & 7;    // 0..7
    // B-loader map: thread = pixel
    const int pn = tid;           // 0..255
    const int ph = h0 + (pn >> 6);
    const int pw = pn & 63;

    float acc[4][8][4];
    #pragma unroll
    for (int mt = 0; mt < 4; ++mt)
        #pragma unroll
        for (int nt = 0; nt < 8; ++nt)
            #pragma unroll
            for (int q = 0; q < 4; ++q) acc[mt][nt][q] = 0.f;

    float4 areg[4];
    float  breg[32];

    // ---- chunk loaders (into registers) ----
    auto load_chunk = [&](int c) {
        const int kbase = c * 32;
        // A: weights [COUT][KTOT]
        #pragma unroll
        for (int p = 0; p < 4; ++p) {
            const int oc = mbase + p * 32 + a_ocl;
            const int k  = kbase + 4 * a_kq;
            float4 v = make_float4(0.f, 0.f, 0.f, 0.f);
            if (oc < COUT && k < KTOT)
                v = *reinterpret_cast<const float4*>(wgt + (size_t)oc * KTOT + k);
            areg[p] = v;
        }
        // B: im2col, interleaved gather pattern
        int ic0 = 0, rem0 = 0;
        if (KH == 3) { ic0 = kbase / 9; rem0 = kbase - ic0 * 9; }
        #pragma unroll
        for (int r = 0; r < 8; ++r) {
            #pragma unroll
            for (int j = 0; j < 4; ++j) {
                const int kin = 8 * (r >> 1) + 2 * (r & 1) + (j >> 1) + 4 * (j & 1);
                const int k   = kbase + kin;
                float v = 0.f;
                if ((KTOT % 32 == 0) || (k < KTOT)) {
                    if (KH == 3) {
                        int t = rem0 + kin;
                        int ica = t / 9;
                        int rr = t - ica * 9;
                        int dh = rr / 3 - 1;
                        int dw = rr - (rr / 3) * 3 - 1;
                        int hh = ph + dh, ww = pw + dw;
                        if (hh >= 0 && hh < HH_ && ww >= 0 && ww < WW_)
                            v = inb[((size_t)(ic0 + ica) * HH_ + hh) * WW_ + ww];
                    } else {
                        v = inb[((size_t)k * HH_ + ph) * WW_ + pw];
                    }
                }
                breg[r * 4 + j] = v;
            }
        }
    };

    auto store_chunk = [&](int s) {
        float* As = smemf + s * STAGE_WORDS;
        float* Bs = As + A_WORDS;
        #pragma unroll
        for (int p = 0; p < 4; ++p) {
            const int m = p * 32 + a_ocl;
            const int x = (m & 3) << 3;
            uint4 w;
            w.x = cvt_tf32(areg[p].x); w.y = cvt_tf32(areg[p].y);
            w.z = cvt_tf32(areg[p].z); w.w = cvt_tf32(areg[p].w);
            *reinterpret_cast<uint4*>(&As[m * 32 + ((4 * a_kq) ^ x)]) = w;
        }
        const int xb = (pn & 3) << 3;
        #pragma unroll
        for (int r = 0; r < 8; ++r) {
            uint4 w;
            w.x = cvt_tf32(breg[r * 4 + 0]); w.y = cvt_tf32(breg[r * 4 + 1]);
            w.z = cvt_tf32(breg[r * 4 + 2]); w.w = cvt_tf32(breg[r * 4 + 3]);
            *reinterpret_cast<uint4*>(&Bs[pn * 32 + ((4 * r) ^ xb)]) = w;
        }
    };

    // ---- pipeline ----
    load_chunk(0);
    store_chunk(0);
    __syncthreads();

    for (int c = 0; c < NC; ++c) {
        if (c + 1 < NC) load_chunk(c + 1);

        const float* As = smemf + (c & 1) * STAGE_WORDS;
        const float* Bs = As + A_WORDS;
        const int xa = (g & 3) << 3;

        #pragma unroll
        for (int step = 0; step < 4; ++step) {
            const int K0 = step * 8;
            uint32_t af[4][4];
            #pragma unroll
            for (int mt = 0; mt < 4; ++mt) {
                const int m0 = wm + mt * 16 + g;
                af[mt][0] = __float_as_uint(As[(m0    ) * 32 + ((K0 + tq    ) ^ xa)]);
                af[mt][1] = __float_as_uint(As[(m0 + 8) * 32 + ((K0 + tq    ) ^ xa)]);
                af[mt][2] = __float_as_uint(As[(m0    ) * 32 + ((K0 + tq + 4) ^ xa)]);
                af[mt][3] = __float_as_uint(As[(m0 + 8) * 32 + ((K0 + tq + 4) ^ xa)]);
            }
            #pragma unroll
            for (int nt = 0; nt < 8; ++nt) {
                const int n = wn + nt * 8 + g;
                float2 bb = *reinterpret_cast<const float2*>(
                    &Bs[n * 32 + ((K0 + 2 * tq) ^ ((n & 3) << 3))]);
                const uint32_t b0 = __float_as_uint(bb.x);
                const uint32_t b1 = __float_as_uint(bb.y);
                #pragma unroll
                for (int mt = 0; mt < 4; ++mt)
                    mma_tf32(acc[mt][nt], af[mt][0], af[mt][1], af[mt][2], af[mt][3], b0, b1);
            }
        }
        __syncthreads();
        if (c + 1 < NC) {
            store_chunk((c + 1) & 1);
            __syncthreads();
        }
    }

    // ---- epilogue ----
    #pragma unroll
    for (int mt = 0; mt < 4; ++mt) {
        const int ocl = mbase + wm + mt * 16 + g;
        const int och = ocl + 8;
        const float bl = (ocl < COUT) ? bias[ocl] : 0.f;
        const float bh = (och < COUT) ? bias[och] : 0.f;
        float* opl = out + ((size_t)b * COUT + ocl) * HW_ + pix0;
        float* oph = out + ((size_t)b * COUT + och) * HW_ + pix0;
        #pragma unroll
        for (int nt = 0; nt < 8; ++nt) {
            const int col = wn + nt * 8 + 2 * tq;
            float2 vl, vh;
            vl.x = acc[mt][nt][0] + bl; vl.y = acc[mt][nt][1] + bl;
            vh.x = acc[mt][nt][2] + bh; vh.y = acc[mt][nt][3] + bh;
            if (RELU) {
                vl.x = fmaxf(vl.x, 0.f); vl.y = fmaxf(vl.y, 0.f);
                vh.x = fmaxf(vh.x, 0.f); vh.y = fmaxf(vh.y, 0.f);
            }
            if (ocl < COUT) *reinterpret_cast<float2*>(opl + col) = vl;
            if (och < COUT) *reinterpret_cast<float2*>(oph + col) = vh;
        }
    }
}

// ---------------- RQS pointwise transform ----------------
__device__ __forceinline__ float softplusf(float v) {
    return (v > 20.f) ? v : log1pf(expf(v));
}

__global__ void rqs_kernel(const float* __restrict__ x, float* __restrict__ y)
{
    int i = blockIdx.x * blockDim.x + threadIdx.x;
    if (i >= NTOT) return;
    int hw = i & (HW_ - 1);
    int bc = i >> 12;          // b*CC + c
    int c = bc % CC;
    int b = bc / CC;
    const float* pp = g_params + (((size_t)b * OUTS + c * 23) * HW_) + hw;

    float xv = x[i];
    bool inside = (xv >= -TAILF) && (xv <= TAILF);
    float xin = fminf(fmaxf(xv, -TAILF), TAILF);

    float u[NB];
    float mx = -1e30f;
    #pragma unroll
    for (int j = 0; j < NB; ++j) { u[j] = pp[(size_t)j * HW_]; mx = fmaxf(mx, u[j]); }
    float se = 0.f;
    #pragma unroll
    for (int j = 0; j < NB; ++j) { u[j] = expf(u[j] - mx); se += u[j]; }
    float inv = 1.f / se;
    float cw[NB + 1];
    cw[0] = -TAILF;
    float cs = 0.f;
    #pragma unroll
    for (int k = 0; k < NB; ++k) {
        cs += MBWF + (1.f - MBWF * NB) * (u[k] * inv);
        cw[k + 1] = 2.f * TAILF * cs - TAILF;
    }
    cw[NB] = TAILF;

    int t = 0;
    #pragma unroll
    for (int k = 1; k < NB; ++k) t += (xin >= cw[k]) ? 1 : 0;
    float in_cw = cw[t];
    float in_w  = cw[t + 1] - cw[t];

    mx = -1e30f;
    #pragma unroll
    for (int j = 0; j < NB; ++j) { u[j] = pp[(size_t)(NB + j) * HW_]; mx = fmaxf(mx, u[j]); }
    se = 0.f;
    #pragma unroll
    for (int j = 0; j < NB; ++j) { u[j] = expf(u[j] - mx); se += u[j]; }
    inv = 1.f / se;
    float ch[NB + 1];
    ch[0] = -TAILF;
    cs = 0.f;
    #pragma unroll
    for (int k = 0; k < NB; ++k) {
        cs += MBHF + (1.f - MBHF * NB) * (u[k] * inv);
        ch[k + 1] = 2.f * TAILF * cs - TAILF;
    }
    ch[NB] = TAILF;
    float in_ch = ch[t];
    float in_h  = ch[t + 1] - ch[t];

    float d0 = 1.0f, d1 = 1.0f;
    if (t > 0)      d0 = MDF + softplusf(pp[(size_t)(2*NB + t - 1) * HW_]);
    if (t < NB - 1) d1 = MDF + softplusf(pp[(size_t)(2*NB + t) * HW_]);

    float delta = in_h / in_w;
    float th  = (xin - in_cw) / in_w;
    float tom = th * (1.f - th);
    float numer = in_h * (delta * th * th + d0 * tom);
    float denom = delta + (d0 + d1 - 2.f * delta) * tom;
    float yv = in_ch + numer / denom;
    float omt = 1.f - th;
    float dnum = delta * delta * (d1 * th * th + 2.f * delta * tom + d0 * omt * omt);
    float lad = logf(dnum) - 2.f * logf(denom);

    y[i] = inside ? yv : xv;
    g_lad[i] = inside ? lad : 0.f;
}

// ---------------- deterministic per-batch logdet reduction ----------------
__global__ void logdet_reduce(const float* __restrict__ logdet, float* __restrict__ out)
{
    int b = blockIdx.x;
    const float* p = g_lad + (size_t)b * PERB;
    double s = 0.0;
    for (int i = threadIdx.x; i < PERB; i += 256) s += (double)p[i];
    __shared__ double sm[256];
    sm[threadIdx.x] = s;
    __syncthreads();
    for (int st = 128; st > 0; st >>= 1) {
        if (threadIdx.x < st) sm[threadIdx.x] += sm[threadIdx.x + st];
        __syncthreads();
    }
    if (threadIdx.x == 0) out[b] = logdet[b] + (float)sm[0];
}

// ---------------- launch ----------------
#define CONV_SMEM (2 * 48 * 1024)

extern "C" void kernel_launch(void* const* d_in, const int* in_sizes, int n_in,
                              void* d_out, int out_size)
{
    const float* x    = (const float*)d_in[0];
    const float* ld   = (const float*)d_in[1];
    const float* cond = (const float*)d_in[2];
    const float* w1   = (const float*)d_in[3];
    const float* b1   = (const float*)d_in[4];
    const float* w2   = (const float*)d_in[5];
    const float* b2   = (const float*)d_in[6];
    const float* w3   = (const float*)d_in[7];
    const float* b3   = (const float*)d_in[8];
    float* out = (float*)d_out;

    float *p_netin, *p_h1, *p_h2, *p_params;
    cudaGetSymbolAddress((void**)&p_netin, g_netin);
    cudaGetSymbolAddress((void**)&p_h1, g_h1);
    cudaGetSymbolAddress((void**)&p_h2, g_h2);
    cudaGetSymbolAddress((void**)&p_params, g_params);

    cudaFuncSetAttribute(conv_mma<3, true,  HID,  144>,  cudaFuncAttributeMaxDynamicSharedMemorySize, CONV_SMEM);
    cudaFuncSetAttribute(conv_mma<1, true,  HID,  128>,  cudaFuncAttributeMaxDynamicSharedMemorySize, CONV_SMEM);
    cudaFuncSetAttribute(conv_mma<3, false, OUTS, 1152>, cudaFuncAttributeMaxDynamicSharedMemorySize, CONV_SMEM);

    {
        const int N = BB * CIN1 * HW_;
        concat_kernel<<<(N + 255) / 256, 256>>>(x, cond);
    }
    conv_mma<3, true,  HID,  144 ><<<dim3(16, 1, BB), 256, CONV_SMEM>>>(p_netin, w1, b1, p_h1);
    conv_mma<1, true,  HID,  128 ><<<dim3(16, 1, BB), 256, CONV_SMEM>>>(p_h1,    w2, b2, p_h2);
    conv_mma<3, false, OUTS, 1152><<<dim3(16, 3, BB), 256, CONV_SMEM>>>(p_h2,    w3, b3, p_params);
    rqs_kernel<<<(NTOT + 255) / 256, 256>>>(x, out);
    logdet_reduce<<<BB, 256>>>(ld, out + NTOT);
}

// round 5
// speedup vs baseline: 3.0628x; 1.3360x over previous
#include <cuda_runtime.h>
#include <cuda_bf16.h>
#include <math.h>
#include <cstdint>

// Problem constants
#define BB    32
#define CC    12
#define HH_   64
#define WW_   64
#define HW_   4096
#define HID   128
#define CONDC 4
#define CIN1  16
#define OUTS  276          // 12 * 23
#define NB    8
#define TAILF 3.0f
#define MBWF  0.001f
#define MBHF  0.001f
#define MDF   0.001f
#define NTOT  (BB*CC*HW_)  // 1572864
#define PERB  (CC*HW_)     // 49152

// ---------------- scratch (no cudaMalloc allowed) ----------------
__device__ float g_netin[(size_t)BB*CIN1*HW_];
__device__ float g_h1[(size_t)BB*HID*HW_];
__device__ float g_h2[(size_t)BB*HID*HW_];
__device__ float g_params[(size_t)BB*OUTS*HW_];
__device__ float g_lad[(size_t)NTOT];

// ---------------- helpers ----------------
__device__ __forceinline__ uint32_t smem_u32(const void* p) {
    uint32_t a;
    asm("{ .reg .u64 t; cvta.to.shared.u64 t, %1; cvt.u32.u64 %0, t; }" : "=r"(a) : "l"(p));
    return a;
}

__device__ __forceinline__ void cp_async16(uint32_t dst, const void* src, int bytes) {
    asm volatile("cp.async.cg.shared.global [%0], [%1], 16, %2;"
                 :: "r"(dst), "l"(src), "r"(bytes) : "memory");
}
__device__ __forceinline__ void cp_commit() {
    asm volatile("cp.async.commit_group;" ::: "memory");
}
__device__ __forceinline__ void cp_wait0() {
    asm volatile("cp.async.wait_group 0;" ::: "memory");
}

__device__ __forceinline__ void mma_tf32(float c[4],
                                         uint32_t a0, uint32_t a1, uint32_t a2, uint32_t a3,
                                         uint32_t b0, uint32_t b1) {
    asm volatile(
        "mma.sync.aligned.m16n8k8.row.col.f32.tf32.tf32.f32 "
        "{%0,%1,%2,%3}, {%4,%5,%6,%7}, {%8,%9}, {%0,%1,%2,%3};"
        : "+f"(c[0]), "+f"(c[1]), "+f"(c[2]), "+f"(c[3])
        : "r"(a0), "r"(a1), "r"(a2), "r"(a3), "r"(b0), "r"(b1));
}

// ---------------- concat x + conditioning ----------------
__global__ void concat_kernel(const float* __restrict__ x, const float* __restrict__ cond) {
    int i = blockIdx.x * blockDim.x + threadIdx.x;
    const int N = BB * CIN1 * HW_;
    if (i >= N) return;
    int hw = i & (HW_ - 1);
    int bc = i >> 12;
    int c = bc % CIN1;
    int b = bc / CIN1;
    float v;
    if (c < CC) v = x[((size_t)b*CC + c)*HW_ + hw];
    else        v = cond[((size_t)b*CONDC + (c - CC))*HW_ + hw];
    g_netin[i] = v;
}

// ---------------- tf32 mma.sync implicit-GEMM conv ----------------
// CTA: 256 threads (8 warps, 2(M) x 4(N)), tile M=128 oc x N=256 pixels, BK=32.
// A loaded via cp.async (raw fp32 -> tf32 truncation in HW), B via table-driven
// im2col gather. Double-buffered smem, register-prefetch of next B chunk.
#define STAGE_WORDS (48 * 1024 / 4)
#define A_WORDS     (128 * 32)

template<int KH, bool RELU, int COUT, int KTOT>
__global__ __launch_bounds__(256, 1)
void conv_mma(const float* __restrict__ in, const float* __restrict__ wgt,
              const float* __restrict__ bias, float* __restrict__ out)
{
    constexpr int NC  = (KTOT + 31) / 32;
    constexpr int CIN = KTOT / (KH * KH);
    constexpr int TBLW = (KH == 3) ? NC * 32 * 2 : 0;   // int2 per k
    extern __shared__ float smemf[];
    float* stages = smemf + TBLW;

    const int tid  = threadIdx.x;
    const int wid  = tid >> 5;
    const int lane = tid & 31;
    const int g    = lane >> 2;   // 0..7
    const int tq   = lane & 3;    // 0..3
    const int wm   = (wid & 1) * 64;
    const int wn   = (wid >> 1) * 64;

    const int b     = blockIdx.z;
    const int mbase = blockIdx.y * 128;
    const int h0    = blockIdx.x * 4;         // 4 image rows = 256 pixels
    const int pix0  = blockIdx.x * 256;

    const float* inb = in + (size_t)b * CIN * HW_;

    // A-loader map
    const int a_ocl = tid >> 3;   // 0..31
    const int a_kq  = tid & 7;    // 0..7
    // B-loader map: thread = pixel
    const int pn  = tid;
    const int ph  = h0 + (pn >> 6);
    const int pw  = pn & 63;
    const int phw = ph * WW_ + pw;

    // ---- im2col table (KH==3 only) ----
    int2* tbl = reinterpret_cast<int2*>(smemf);
    if (KH == 3) {
        for (int k = tid; k < NC * 32; k += 256) {
            int2 e;
            if (k < KTOT) {
                int ic = k / 9;
                int r  = k - ic * 9;
                int dh = r / 3;
                int dw = r - dh * 3;
                e.x = ic * HW_ + (dh - 1) * WW_ + (dw - 1);
                e.y = dh | (dw << 8);
            } else {
                e.x = 0; e.y = 0xFFFF;
            }
            tbl[k] = e;
        }
        __syncthreads();
    }

    float acc[4][8][4];
    #pragma unroll
    for (int mt = 0; mt < 4; ++mt)
        #pragma unroll
        for (int nt = 0; nt < 8; ++nt)
            #pragma unroll
            for (int q = 0; q < 4; ++q) acc[mt][nt][q] = 0.f;

    float breg[32];

    // ---- A prefetch via cp.async (writes stage (c&1)) ----
    auto prefetchA = [&](int c) {
        const int kbase = c * 32;
        float* As = stages + (c & 1) * STAGE_WORDS;
        const int k = kbase + 4 * a_kq;
        #pragma unroll
        for (int p = 0; p < 4; ++p) {
            const int m  = p * 32 + a_ocl;
            const int oc = mbase + m;
            const bool ok = (oc < COUT) && (k < KTOT);
            const float* src = ok ? (wgt + (size_t)oc * KTOT + k) : wgt;
            uint32_t dst = smem_u32(&As[m * 32 + ((4 * a_kq) ^ ((m & 3) << 3))]);
            cp_async16(dst, src, ok ? 16 : 0);
        }
        cp_commit();
    };

    // ---- B gather into registers ----
    auto load_chunkB = [&](int c) {
        const int kbase = c * 32;
        #pragma unroll
        for (int r = 0; r < 8; ++r) {
            #pragma unroll
            for (int j = 0; j < 4; ++j) {
                const int kin = 8 * (r >> 1) + 2 * (r & 1) + (j >> 1) + 4 * (j & 1);
                const int k   = kbase + kin;
                float v = 0.f;
                if (KH == 3) {
                    int2 e = tbl[k];
                    int dh = (e.y & 0xFF) - 1;
                    int dw = (e.y >> 8) - 1;
                    if ((unsigned)(ph + dh) < (unsigned)HH_ &&
                        (unsigned)(pw + dw) < (unsigned)WW_)
                        v = inb[e.x + phw];
                } else {
                    v = inb[(size_t)k * HW_ + phw];
                }
                breg[r * 4 + j] = v;
            }
        }
    };

    auto store_chunkB = [&](int s) {
        float* Bs = stages + s * STAGE_WORDS + A_WORDS;
        const int xb = (pn & 3) << 3;
        #pragma unroll
        for (int r = 0; r < 8; ++r) {
            *reinterpret_cast<float4*>(&Bs[pn * 32 + ((4 * r) ^ xb)]) =
                make_float4(breg[r*4+0], breg[r*4+1], breg[r*4+2], breg[r*4+3]);
        }
    };

    // ---- pipeline ----
    prefetchA(0);
    load_chunkB(0);
    store_chunkB(0);
    cp_wait0();
    __syncthreads();

    for (int c = 0; c < NC; ++c) {
        if (c + 1 < NC) { prefetchA(c + 1); load_chunkB(c + 1); }

        const float* As = stages + (c & 1) * STAGE_WORDS;
        const float* Bs = As + A_WORDS;
        const int xa = (g & 3) << 3;

        #pragma unroll
        for (int step = 0; step < 4; ++step) {
            const int K0 = step * 8;
            uint32_t af[4][4];
            #pragma unroll
            for (int mt = 0; mt < 4; ++mt) {
                const int m0 = wm + mt * 16 + g;
                af[mt][0] = __float_as_uint(As[(m0    ) * 32 + ((K0 + tq    ) ^ xa)]);
                af[mt][1] = __float_as_uint(As[(m0 + 8) * 32 + ((K0 + tq    ) ^ xa)]);
                af[mt][2] = __float_as_uint(As[(m0    ) * 32 + ((K0 + tq + 4) ^ xa)]);
                af[mt][3] = __float_as_uint(As[(m0 + 8) * 32 + ((K0 + tq + 4) ^ xa)]);
            }
            #pragma unroll
            for (int nt = 0; nt < 8; ++nt) {
                const int n = wn + nt * 8 + g;
                float2 bb = *reinterpret_cast<const float2*>(
                    &Bs[n * 32 + ((K0 + 2 * tq) ^ ((n & 3) << 3))]);
                const uint32_t b0 = __float_as_uint(bb.x);
                const uint32_t b1 = __float_as_uint(bb.y);
                #pragma unroll
                for (int mt = 0; mt < 4; ++mt)
                    mma_tf32(acc[mt][nt], af[mt][0], af[mt][1], af[mt][2], af[mt][3], b0, b1);
            }
        }
        __syncthreads();
        if (c + 1 < NC) {
            store_chunkB((c + 1) & 1);
            cp_wait0();
            __syncthreads();
        }
    }

    // ---- epilogue ----
    #pragma unroll
    for (int mt = 0; mt < 4; ++mt) {
        const int ocl = mbase + wm + mt * 16 + g;
        const int och = ocl + 8;
        const float bl = (ocl < COUT) ? bias[ocl] : 0.f;
        const float bh = (och < COUT) ? bias[och] : 0.f;
        float* opl = out + ((size_t)b * COUT + ocl) * HW_ + pix0;
        float* oph = out + ((size_t)b * COUT + och) * HW_ + pix0;
        #pragma unroll
        for (int nt = 0; nt < 8; ++nt) {
            const int col = wn + nt * 8 + 2 * tq;
            float2 vl, vh;
            vl.x = acc[mt][nt][0] + bl; vl.y = acc[mt][nt][1] + bl;
            vh.x = acc[mt][nt][2] + bh; vh.y = acc[mt][nt][3] + bh;
            if (RELU) {
                vl.x = fmaxf(vl.x, 0.f); vl.y = fmaxf(vl.y, 0.f);
                vh.x = fmaxf(vh.x, 0.f); vh.y = fmaxf(vh.y, 0.f);
            }
            if (ocl < COUT) *reinterpret_cast<float2*>(opl + col) = vl;
            if (och < COUT) *reinterpret_cast<float2*>(oph + col) = vh;
        }
    }
}

// ---------------- RQS pointwise transform (fast math) ----------------
__device__ __forceinline__ float softplusf(float v) {
    return (v > 20.f) ? v : __logf(1.f + __expf(v));
}

__global__ void rqs_kernel(const float* __restrict__ x, float* __restrict__ y)
{
    int i = blockIdx.x * blockDim.x + threadIdx.x;
    if (i >= NTOT) return;
    int hw = i & (HW_ - 1);
    int bc = i >> 12;          // b*CC + c
    int c = bc % CC;
    int b = bc / CC;
    const float* pp = g_params + (((size_t)b * OUTS + c * 23) * HW_) + hw;

    float xv = x[i];
    bool inside = (xv >= -TAILF) && (xv <= TAILF);
    float xin = fminf(fmaxf(xv, -TAILF), TAILF);

    float u[NB];
    float mx = -1e30f;
    #pragma unroll
    for (int j = 0; j < NB; ++j) { u[j] = pp[(size_t)j * HW_]; mx = fmaxf(mx, u[j]); }
    float se = 0.f;
    #pragma unroll
    for (int j = 0; j < NB; ++j) { u[j] = __expf(u[j] - mx); se += u[j]; }
    float inv = 1.f / se;
    float cw[NB + 1];
    cw[0] = -TAILF;
    float cs = 0.f;
    #pragma unroll
    for (int k = 0; k < NB; ++k) {
        cs += MBWF + (1.f - MBWF * NB) * (u[k] * inv);
        cw[k + 1] = 2.f * TAILF * cs - TAILF;
    }
    cw[NB] = TAILF;

    int t = 0;
    #pragma unroll
    for (int k = 1; k < NB; ++k) t += (xin >= cw[k]) ? 1 : 0;
    float in_cw = cw[t];
    float in_w  = cw[t + 1] - cw[t];

    mx = -1e30f;
    #pragma unroll
    for (int j = 0; j < NB; ++j) { u[j] = pp[(size_t)(NB + j) * HW_]; mx = fmaxf(mx, u[j]); }
    se = 0.f;
    #pragma unroll
    for (int j = 0; j < NB; ++j) { u[j] = __expf(u[j] - mx); se += u[j]; }
    inv = 1.f / se;
    float ch[NB + 1];
    ch[0] = -TAILF;
    cs = 0.f;
    #pragma unroll
    for (int k = 0; k < NB; ++k) {
        cs += MBHF + (1.f - MBHF * NB) * (u[k] * inv);
        ch[k + 1] = 2.f * TAILF * cs - TAILF;
    }
    ch[NB] = TAILF;
    float in_ch = ch[t];
    float in_h  = ch[t + 1] - ch[t];

    float d0 = 1.0f, d1 = 1.0f;
    if (t > 0)      d0 = MDF + softplusf(pp[(size_t)(2*NB + t - 1) * HW_]);
    if (t < NB - 1) d1 = MDF + softplusf(pp[(size_t)(2*NB + t) * HW_]);

    float delta = in_h / in_w;
    float th  = (xin - in_cw) / in_w;
    float tom = th * (1.f - th);
    float numer = in_h * (delta * th * th + d0 * tom);
    float denom = delta + (d0 + d1 - 2.f * delta) * tom;
    float yv = in_ch + numer / denom;
    float omt = 1.f - th;
    float dnum = delta * delta * (d1 * th * th + 2.f * delta * tom + d0 * omt * omt);
    float lad = __logf(dnum) - 2.f * __logf(denom);

    y[i] = inside ? yv : xv;
    g_lad[i] = inside ? lad : 0.f;
}

// ---------------- deterministic per-batch logdet reduction ----------------
__global__ void logdet_reduce(const float* __restrict__ logdet, float* __restrict__ out)
{
    int b = blockIdx.x;
    const float* p = g_lad + (size_t)b * PERB;
    double s = 0.0;
    for (int i = threadIdx.x; i < PERB; i += 256) s += (double)p[i];
    __shared__ double sm[256];
    sm[threadIdx.x] = s;
    __syncthreads();
    for (int st = 128; st > 0; st >>= 1) {
        if (threadIdx.x < st) sm[threadIdx.x] += sm[threadIdx.x + st];
        __syncthreads();
    }
    if (threadIdx.x == 0) out[b] = logdet[b] + (float)sm[0];
}

// ---------------- launch ----------------
#define SMEM1 ((5  * 32 * 2 + 2 * STAGE_WORDS) * 4)
#define SMEM2 ((              2 * STAGE_WORDS) * 4)
#define SMEM3 ((36 * 32 * 2 + 2 * STAGE_WORDS) * 4)

extern "C" void kernel_launch(void* const* d_in, const int* in_sizes, int n_in,
                              void* d_out, int out_size)
{
    const float* x    = (const float*)d_in[0];
    const float* ld   = (const float*)d_in[1];
    const float* cond = (const float*)d_in[2];
    const float* w1   = (const float*)d_in[3];
    const float* b1   = (const float*)d_in[4];
    const float* w2   = (const float*)d_in[5];
    const float* b2   = (const float*)d_in[6];
    const float* w3   = (const float*)d_in[7];
    const float* b3   = (const float*)d_in[8];
    float* out = (float*)d_out;

    float *p_netin, *p_h1, *p_h2, *p_params;
    cudaGetSymbolAddress((void**)&p_netin, g_netin);
    cudaGetSymbolAddress((void**)&p_h1, g_h1);
    cudaGetSymbolAddress((void**)&p_h2, g_h2);
    cudaGetSymbolAddress((void**)&p_params, g_params);

    cudaFuncSetAttribute(conv_mma<3, true,  HID,  144>,  cudaFuncAttributeMaxDynamicSharedMemorySize, SMEM1);
    cudaFuncSetAttribute(conv_mma<1, true,  HID,  128>,  cudaFuncAttributeMaxDynamicSharedMemorySize, SMEM2);
    cudaFuncSetAttribute(conv_mma<3, false, OUTS, 1152>, cudaFuncAttributeMaxDynamicSharedMemorySize, SMEM3);

    {
        const int N = BB * CIN1 * HW_;
        concat_kernel<<<(N + 255) / 256, 256>>>(x, cond);
    }
    conv_mma<3, true,  HID,  144 ><<<dim3(16, 1, BB), 256, SMEM1>>>(p_netin, w1, b1, p_h1);
    conv_mma<1, true,  HID,  128 ><<<dim3(16, 1, BB), 256, SMEM2>>>(p_h1,    w2, b2, p_h2);
    conv_mma<3, false, OUTS, 1152><<<dim3(16, 3, BB), 256, SMEM3>>>(p_h2,    w3, b3, p_params);
    rqs_kernel<<<(NTOT + 255) / 256, 256>>>(x, out);
    logdet_reduce<<<BB, 256>>>(ld, out + NTOT);
}

// round 6
// speedup vs baseline: 3.1817x; 1.0388x over previous
#include <cuda_runtime.h>
#include <cuda_fp16.h>
#include <math.h>
#include <cstdint>

// Problem constants
#define BB    32
#define CC    12
#define HH_   64
#define WW_   64
#define HW_   4096
#define HID   128
#define CONDC 4
#define CIN1  16
#define OUTS  276          // 12 * 23
#define NB    8
#define TAILF 3.0f
#define MBWF  0.001f
#define MBHF  0.001f
#define MDF   0.001f
#define NTOT  (BB*CC*HW_)  // 1572864
#define PERB  (CC*HW_)     // 49152

// ---------------- scratch (no cudaMalloc allowed) ----------------
__device__ __half g_netin_h[(size_t)BB*CIN1*HW_];
__device__ __half g_h1h[(size_t)BB*HID*HW_];
__device__ __half g_h2h[(size_t)BB*HID*HW_];
__device__ __half g_w1h[128 * 160];
__device__ __half g_w2h[128 * 128];
__device__ __half g_w3h[384 * 1152];
__device__ float  g_params[(size_t)BB*OUTS*HW_];
__device__ float  g_lad[(size_t)NTOT];

// ---------------- helpers ----------------
__device__ __forceinline__ uint32_t smem_u32(const void* p) {
    uint32_t a;
    asm("{ .reg .u64 t; cvta.to.shared.u64 t, %1; cvt.u32.u64 %0, t; }" : "=r"(a) : "l"(p));
    return a;
}
__device__ __forceinline__ void cp_async16(uint32_t dst, const void* src) {
    asm volatile("cp.async.cg.shared.global [%0], [%1], 16;"
                 :: "r"(dst), "l"(src) : "memory");
}
__device__ __forceinline__ void cp_commit() {
    asm volatile("cp.async.commit_group;" ::: "memory");
}
__device__ __forceinline__ void cp_wait0() {
    asm volatile("cp.async.wait_group 0;" ::: "memory");
}
__device__ __forceinline__ void ldsm_x4(uint32_t r[4], uint32_t addr) {
    asm volatile("ldmatrix.sync.aligned.m8n8.x4.shared.b16 {%0,%1,%2,%3}, [%4];"
        : "=r"(r[0]), "=r"(r[1]), "=r"(r[2]), "=r"(r[3]) : "r"(addr));
}
__device__ __forceinline__ void mma_f16(float c[4], const uint32_t a[4],
                                        uint32_t b0, uint32_t b1) {
    asm volatile(
        "mma.sync.aligned.m16n8k16.row.col.f32.f16.f16.f32 "
        "{%0,%1,%2,%3}, {%4,%5,%6,%7}, {%8,%9}, {%0,%1,%2,%3};"
        : "+f"(c[0]), "+f"(c[1]), "+f"(c[2]), "+f"(c[3])
        : "r"(a[0]), "r"(a[1]), "r"(a[2]), "r"(a[3]), "r"(b0), "r"(b1));
}
#define STS128U(addr, a, b, c, d) \
    asm volatile("st.shared.v4.b32 [%0], {%1,%2,%3,%4};" :: "r"(addr), "r"(a), "r"(b), "r"(c), "r"(d) : "memory")

// Swizzled tile addressing: rows of 64B (32 halves), 16B granules XORed by (row>>1)&3.
// Conflict-free for ldmatrix 8-row phases and STS.128 writer phases.
__device__ __forceinline__ uint32_t tile_addr(uint32_t base, int row, int kg) {
    return base + row * 64 + ((kg ^ ((row >> 1) & 3)) << 4);
}

#define A_BYTES     (128 * 64)            // 8 KB
#define B_BYTES     (256 * 64)            // 16 KB
#define STAGE_BYTES (A_BYTES + B_BYTES)   // 24 KB

// ---------------- pre-pass: concat (fp16) + weight conversion ----------------
__global__ void concat_kernel(const float* __restrict__ x, const float* __restrict__ cond) {
    int i = blockIdx.x * blockDim.x + threadIdx.x;
    const int N = BB * CIN1 * HW_;
    if (i >= N) return;
    int hw = i & (HW_ - 1);
    int bc = i >> 12;
    int c = bc % CIN1;
    int b = bc / CIN1;
    float v;
    if (c < CC) v = x[((size_t)b*CC + c)*HW_ + hw];
    else        v = cond[((size_t)b*CONDC + (c - CC))*HW_ + hw];
    g_netin_h[i] = __float2half(v);
}

__global__ void prep_weights(const float* __restrict__ w1, const float* __restrict__ w2,
                             const float* __restrict__ w3) {
    const int N1 = 128 * 160, N2 = 128 * 128, N3 = 384 * 1152;
    int i = blockIdx.x * blockDim.x + threadIdx.x;
    if (i < N1) {
        int row = i / 160, k = i - row * 160;
        g_w1h[i] = __float2half(k < 144 ? w1[row * 144 + k] : 0.f);
    } else if (i < N1 + N2) {
        int j = i - N1;
        g_w2h[j] = __float2half(w2[j]);
    } else if (i < N1 + N2 + N3) {
        int j = i - N1 - N2;
        int row = j / 1152;
        g_w3h[j] = __float2half(row < OUTS ? w3[j] : 0.f);
    }
}

// ---------------- fp16 mma.sync implicit-GEMM conv ----------------
// CTA: 256 threads (8 warps, 2(M) x 4(N)), tile M=128 oc x N=256 pixels, BK=32.
// A via cp.async from pre-padded fp16 weights; B via table-driven im2col gather.
// ldmatrix fragment loads; double-buffered smem.
template<int KH, bool RELU, int COUT, int KTOT, int KPAD, bool HALF_OUT>
__global__ __launch_bounds__(256, 1)
void conv_mma(const __half* __restrict__ in, const __half* __restrict__ wgt,
              const float* __restrict__ bias, void* __restrict__ outp)
{
    constexpr int NC   = KPAD / 32;
    constexpr int CIN  = KTOT / (KH * KH);
    constexpr int TBLI = (KH == 3) ? NC * 32 : 0;
    extern __shared__ float smemf[];
    int* tbli = reinterpret_cast<int*>(smemf);
    const uint32_t stg_u = smem_u32(reinterpret_cast<char*>(smemf) + ((TBLI * 4 + 127) & ~127));

    const int tid  = threadIdx.x;
    const int lane = tid & 31;
    const int wid  = tid >> 5;
    const int wm   = (wid & 1) * 64;
    const int wn   = (wid >> 1) * 64;

    const int b     = blockIdx.z;
    const int mbase = blockIdx.y * 128;
    const int h0    = blockIdx.x * 4;
    const int pix0  = blockIdx.x * 256;

    const __half* inb = in + (size_t)b * CIN * HW_;

    const int pn   = tid;
    const int ph   = h0 + (pn >> 6);
    const int pw   = pn & 63;
    const int phw  = ph * WW_ + pw;
    const __half* inb2 = inb + (phw - 65);   // bias of +65 baked into table offsets

    // 9-tap validity mask (per pixel, computed once)
    unsigned vmask = 0;
    if (KH == 3) {
        #pragma unroll
        for (int r = 0; r < 9; ++r) {
            int dh = r / 3 - 1, dw = r - (r / 3) * 3 - 1;
            if ((unsigned)(ph + dh) < (unsigned)HH_ && (unsigned)(pw + dw) < (unsigned)WW_)
                vmask |= 1u << r;
        }
        for (int k = tid; k < TBLI; k += 256) {
            int v;
            if (k < KTOT) {
                int ic = k / 9, r = k - ic * 9;
                v = (ic * HW_ + (r / 3 - 1) * WW_ + (r - (r / 3) * 3 - 1) + 65) | (r << 24);
            } else v = 15 << 24;
            tbli[k] = v;
        }
        __syncthreads();
    }

    float acc[4][8][4];
    #pragma unroll
    for (int mt = 0; mt < 4; ++mt)
        #pragma unroll
        for (int nt = 0; nt < 8; ++nt)
            #pragma unroll
            for (int q = 0; q < 4; ++q) acc[mt][nt][q] = 0.f;

    // A prefetch: 512 granules (row, kg) over 256 threads, 2 cp.async each
    const int agi = tid * 2;
    auto prefetchA = [&](int c) {
        uint32_t sA = stg_u + (c & 1) * STAGE_BYTES;
        #pragma unroll
        for (int p = 0; p < 2; ++p) {
            int gi = agi + p;
            int row = gi >> 2, kg = gi & 3;
            const __half* src = wgt + (size_t)(mbase + row) * KPAD + c * 32 + kg * 8;
            cp_async16(tile_addr(sA, row, kg), src);
        }
        cp_commit();
    };

    // B gather into packed registers
    uint32_t bp[16];
    auto loadB = [&](int c) {
        const int kbase = c * 32;
        #pragma unroll
        for (int j = 0; j < 32; ++j) {
            unsigned short h = 0;
            if (KH == 3) {
                unsigned e = (unsigned)tbli[kbase + j];
                if ((vmask >> (e >> 24)) & 1)
                    h = __half_as_ushort(inb2[e & 0xFFFFFFu]);
            } else {
                h = __half_as_ushort(inb[(size_t)(kbase + j) * HW_ + phw]);
            }
            if ((j & 1) == 0) bp[j >> 1] = h;
            else              bp[j >> 1] |= (uint32_t)h << 16;
        }
    };
    auto storeB = [&](int s) {
        uint32_t sB = stg_u + s * STAGE_BYTES + A_BYTES;
        #pragma unroll
        for (int g2 = 0; g2 < 4; ++g2)
            STS128U(tile_addr(sB, pn, g2), bp[g2*4+0], bp[g2*4+1], bp[g2*4+2], bp[g2*4+3]);
    };

    // ---- pipeline ----
    prefetchA(0);
    loadB(0);
    storeB(0);
    cp_wait0();
    __syncthreads();

    // ldmatrix lane bases
    const int a_m  = (lane & 7) + ((lane >> 3) & 1) * 8;   // + wm + mt*16
    const int a_kg = lane >> 4;                            // + 2*ks
    const int b_n  = (lane & 7) + ((lane >> 4) & 1) * 8;   // + wn + nt2*16
    const int b_kg = (lane >> 3) & 1;                      // + 2*ks

    for (int c = 0; c < NC; ++c) {
        if (c + 1 < NC) { prefetchA(c + 1); loadB(c + 1); }

        uint32_t sA = stg_u + (c & 1) * STAGE_BYTES;
        uint32_t sB = sA + A_BYTES;

        #pragma unroll
        for (int ks = 0; ks < 2; ++ks) {
            uint32_t af[4][4];
            #pragma unroll
            for (int mt = 0; mt < 4; ++mt)
                ldsm_x4(af[mt], tile_addr(sA, wm + mt * 16 + a_m, 2 * ks + a_kg));
            #pragma unroll
            for (int nt2 = 0; nt2 < 4; ++nt2) {
                uint32_t bf[4];
                ldsm_x4(bf, tile_addr(sB, wn + nt2 * 16 + b_n, 2 * ks + b_kg));
                #pragma unroll
                for (int mt = 0; mt < 4; ++mt) {
                    mma_f16(acc[mt][nt2 * 2 + 0], af[mt], bf[0], bf[1]);
                    mma_f16(acc[mt][nt2 * 2 + 1], af[mt], bf[2], bf[3]);
                }
            }
        }
        __syncthreads();
        if (c + 1 < NC) {
            storeB((c + 1) & 1);
            cp_wait0();
            __syncthreads();
        }
    }

    // ---- epilogue ----
    const int g  = lane >> 2;
    const int tq = lane & 3;
    #pragma unroll
    for (int mt = 0; mt < 4; ++mt) {
        const int ocl = mbase + wm + mt * 16 + g;
        const int och = ocl + 8;
        const float bl = (ocl < COUT) ? bias[ocl] : 0.f;
        const float bh = (och < COUT) ? bias[och] : 0.f;
        #pragma unroll
        for (int nt = 0; nt < 8; ++nt) {
            const int col = wn + nt * 8 + 2 * tq;
            float v0 = acc[mt][nt][0] + bl, v1 = acc[mt][nt][1] + bl;
            float v2 = acc[mt][nt][2] + bh, v3 = acc[mt][nt][3] + bh;
            if (RELU) {
                v0 = fmaxf(v0, 0.f); v1 = fmaxf(v1, 0.f);
                v2 = fmaxf(v2, 0.f); v3 = fmaxf(v3, 0.f);
            }
            if constexpr (HALF_OUT) {
                __half* o = (__half*)outp;
                if (ocl < COUT)
                    *reinterpret_cast<__half2*>(o + ((size_t)b * COUT + ocl) * HW_ + pix0 + col) =
                        __floats2half2_rn(v0, v1);
                if (och < COUT)
                    *reinterpret_cast<__half2*>(o + ((size_t)b * COUT + och) * HW_ + pix0 + col) =
                        __floats2half2_rn(v2, v3);
            } else {
                float* o = (float*)outp;
                if (ocl < COUT)
                    *reinterpret_cast<float2*>(o + ((size_t)b * COUT + ocl) * HW_ + pix0 + col) =
                        make_float2(v0, v1);
                if (och < COUT)
                    *reinterpret_cast<float2*>(o + ((size_t)b * COUT + och) * HW_ + pix0 + col) =
                        make_float2(v2, v3);
            }
        }
    }
}

// ---------------- RQS pointwise transform (fast math) ----------------
__device__ __forceinline__ float softplusf(float v) {
    return (v > 20.f) ? v : __logf(1.f + __expf(v));
}

__global__ void rqs_kernel(const float* __restrict__ x, float* __restrict__ y)
{
    int i = blockIdx.x * blockDim.x + threadIdx.x;
    if (i >= NTOT) return;
    int hw = i & (HW_ - 1);
    int bc = i >> 12;          // b*CC + c
    int c = bc % CC;
    int b = bc / CC;
    const float* pp = g_params + (((size_t)b * OUTS + c * 23) * HW_) + hw;

    float xv = x[i];
    bool inside = (xv >= -TAILF) && (xv <= TAILF);
    float xin = fminf(fmaxf(xv, -TAILF), TAILF);

    float u[NB];
    float mx = -1e30f;
    #pragma unroll
    for (int j = 0; j < NB; ++j) { u[j] = pp[(size_t)j * HW_]; mx = fmaxf(mx, u[j]); }
    float se = 0.f;
    #pragma unroll
    for (int j = 0; j < NB; ++j) { u[j] = __expf(u[j] - mx); se += u[j]; }
    float inv = 1.f / se;
    float cw[NB + 1];
    cw[0] = -TAILF;
    float cs = 0.f;
    #pragma unroll
    for (int k = 0; k < NB; ++k) {
        cs += MBWF + (1.f - MBWF * NB) * (u[k] * inv);
        cw[k + 1] = 2.f * TAILF * cs - TAILF;
    }
    cw[NB] = TAILF;

    int t = 0;
    #pragma unroll
    for (int k = 1; k < NB; ++k) t += (xin >= cw[k]) ? 1 : 0;
    float in_cw = cw[t];
    float in_w  = cw[t + 1] - cw[t];

    mx = -1e30f;
    #pragma unroll
    for (int j = 0; j < NB; ++j) { u[j] = pp[(size_t)(NB + j) * HW_]; mx = fmaxf(mx, u[j]); }
    se = 0.f;
    #pragma unroll
    for (int j = 0; j < NB; ++j) { u[j] = __expf(u[j] - mx); se += u[j]; }
    inv = 1.f / se;
    float ch[NB + 1];
    ch[0] = -TAILF;
    cs = 0.f;
    #pragma unroll
    for (int k = 0; k < NB; ++k) {
        cs += MBHF + (1.f - MBHF * NB) * (u[k] * inv);
        ch[k + 1] = 2.f * TAILF * cs - TAILF;
    }
    ch[NB] = TAILF;
    float in_ch = ch[t];
    float in_h  = ch[t + 1] - ch[t];

    float d0 = 1.0f, d1 = 1.0f;
    if (t > 0)      d0 = MDF + softplusf(pp[(size_t)(2*NB + t - 1) * HW_]);
    if (t < NB - 1) d1 = MDF + softplusf(pp[(size_t)(2*NB + t) * HW_]);

    float delta = in_h / in_w;
    float th  = (xin - in_cw) / in_w;
    float tom = th * (1.f - th);
    float numer = in_h * (delta * th * th + d0 * tom);
    float denom = delta + (d0 + d1 - 2.f * delta) * tom;
    float yv = in_ch + numer / denom;
    float omt = 1.f - th;
    float dnum = delta * delta * (d1 * th * th + 2.f * delta * tom + d0 * omt * omt);
    float lad = __logf(dnum) - 2.f * __logf(denom);

    y[i] = inside ? yv : xv;
    g_lad[i] = inside ? lad : 0.f;
}

// ---------------- deterministic per-batch logdet reduction ----------------
__global__ void logdet_reduce(const float* __restrict__ logdet, float* __restrict__ out)
{
    int b = blockIdx.x;
    const float* p = g_lad + (size_t)b * PERB;
    double s = 0.0;
    for (int i = threadIdx.x; i < PERB; i += 256) s += (double)p[i];
    __shared__ double sm[256];
    sm[threadIdx.x] = s;
    __syncthreads();
    for (int st = 128; st > 0; st >>= 1) {
        if (threadIdx.x < st) sm[threadIdx.x] += sm[threadIdx.x + st];
        __syncthreads();
    }
    if (threadIdx.x == 0) out[b] = logdet[b] + (float)sm[0];
}

// ---------------- launch ----------------
#define SMEM_CONV1 (((5  * 32 * 4 + 127) & ~127) + 2 * STAGE_BYTES)
#define SMEM_CONV2 (2 * STAGE_BYTES)
#define SMEM_CONV3 (((36 * 32 * 4 + 127) & ~127) + 2 * STAGE_BYTES)

extern "C" void kernel_launch(void* const* d_in, const int* in_sizes, int n_in,
                              void* d_out, int out_size)
{
    const float* x    = (const float*)d_in[0];
    const float* ld   = (const float*)d_in[1];
    const float* cond = (const float*)d_in[2];
    const float* w1   = (const float*)d_in[3];
    const float* b1   = (const float*)d_in[4];
    const float* w2   = (const float*)d_in[5];
    const float* b2   = (const float*)d_in[6];
    const float* w3   = (const float*)d_in[7];
    const float* b3   = (const float*)d_in[8];
    float* out = (float*)d_out;

    __half *p_netin, *p_h1, *p_h2, *p_w1, *p_w2, *p_w3;
    float *p_params;
    cudaGetSymbolAddress((void**)&p_netin, g_netin_h);
    cudaGetSymbolAddress((void**)&p_h1, g_h1h);
    cudaGetSymbolAddress((void**)&p_h2, g_h2h);
    cudaGetSymbolAddress((void**)&p_w1, g_w1h);
    cudaGetSymbolAddress((void**)&p_w2, g_w2h);
    cudaGetSymbolAddress((void**)&p_w3, g_w3h);
    cudaGetSymbolAddress((void**)&p_params, g_params);

    cudaFuncSetAttribute((const void*)conv_mma<3, true,  HID,  144,  160,  true >,
                         cudaFuncAttributeMaxDynamicSharedMemorySize, SMEM_CONV1);
    cudaFuncSetAttribute((const void*)conv_mma<1, true,  HID,  128,  128,  true >,
                         cudaFuncAttributeMaxDynamicSharedMemorySize, SMEM_CONV2);
    cudaFuncSetAttribute((const void*)conv_mma<3, false, OUTS, 1152, 1152, false>,
                         cudaFuncAttributeMaxDynamicSharedMemorySize, SMEM_CONV3);

    {
        const int N = BB * CIN1 * HW_;
        concat_kernel<<<(N + 255) / 256, 256>>>(x, cond);
    }
    {
        const int NW = 128*160 + 128*128 + 384*1152;
        prep_weights<<<(NW + 255) / 256, 256>>>(w1, w2, w3);
    }
    conv_mma<3, true,  HID,  144,  160,  true ><<<dim3(16, 1, BB), 256, SMEM_CONV1>>>(p_netin, p_w1, b1, p_h1);
    conv_mma<1, true,  HID,  128,  128,  true ><<<dim3(16, 1, BB), 256, SMEM_CONV2>>>(p_h1,    p_w2, b2, p_h2);
    conv_mma<3, false, OUTS, 1152, 1152, false><<<dim3(16, 3, BB), 256, SMEM_CONV3>>>(p_h2,    p_w3, b3, p_params);
    rqs_kernel<<<(NTOT + 255) / 256, 256>>>(x, out);
    logdet_reduce<<<BB, 256>>>(ld, out + NTOT);
}

// round 7
// speedup vs baseline: 4.8719x; 1.5312x over previous
#include <cuda_runtime.h>
#include <cuda_fp16.h>
#include <math.h>
#include <cstdint>

// Problem constants
#define BB    32
#define CC    12
#define HH_   64
#define WW_   64
#define HW_   4096
#define HID   128
#define CONDC 4
#define OUTS  276          // 12 * 23
#define NB    8
#define TAILF 3.0f
#define MBWF  0.001f
#define MBHF  0.001f
#define MDF   0.001f
#define NTOT  (BB*CC*HW_)  // 1572864
#define PERB  (CC*HW_)     // 49152
#define PAREA (66*64)      // padded channel area (66 rows x 64 cols)

// ---------------- scratch (no cudaMalloc allowed) ----------------
__device__ __half g_pad1[(size_t)3*BB*16*PAREA];     // 13 MB   (x||cond, dw-replicated, padded)
__device__ __half g_h1h[(size_t)BB*HID*HW_];          // 33 MB
__device__ __half g_pad3[(size_t)3*BB*HID*PAREA];    // 104 MB  (h2, dw-replicated, padded)
__device__ __half g_w1h[128 * 160];
__device__ __half g_w2h[128 * 128];
__device__ __half g_w3h[384 * 1152];
__device__ float  g_params[(size_t)BB*OUTS*HW_];      // 144 MB
__device__ float  g_lad[(size_t)NTOT];

// ---------------- helpers ----------------
__device__ __forceinline__ uint32_t smem_u32(const void* p) {
    uint32_t a;
    asm("{ .reg .u64 t; cvta.to.shared.u64 t, %1; cvt.u32.u64 %0, t; }" : "=r"(a) : "l"(p));
    return a;
}
__device__ __forceinline__ void cp_async16(uint32_t dst, const void* src) {
    asm volatile("cp.async.cg.shared.global [%0], [%1], 16;"
                 :: "r"(dst), "l"(src) : "memory");
}
__device__ __forceinline__ void cp_commit() {
    asm volatile("cp.async.commit_group;" ::: "memory");
}
__device__ __forceinline__ void cp_wait2() {
    asm volatile("cp.async.wait_group 2;" ::: "memory");
}
__device__ __forceinline__ void ldsm_x4(uint32_t r[4], uint32_t addr) {
    asm volatile("ldmatrix.sync.aligned.m8n8.x4.shared.b16 {%0,%1,%2,%3}, [%4];"
        : "=r"(r[0]), "=r"(r[1]), "=r"(r[2]), "=r"(r[3]) : "r"(addr));
}
__device__ __forceinline__ void ldsm_x4t(uint32_t r[4], uint32_t addr) {
    asm volatile("ldmatrix.sync.aligned.m8n8.x4.trans.shared.b16 {%0,%1,%2,%3}, [%4];"
        : "=r"(r[0]), "=r"(r[1]), "=r"(r[2]), "=r"(r[3]) : "r"(addr));
}
__device__ __forceinline__ void mma_f16(float c[4], const uint32_t a[4],
                                        uint32_t b0, uint32_t b1) {
    asm volatile(
        "mma.sync.aligned.m16n8k16.row.col.f32.f16.f16.f32 "
        "{%0,%1,%2,%3}, {%4,%5,%6,%7}, {%8,%9}, {%0,%1,%2,%3};"
        : "+f"(c[0]), "+f"(c[1]), "+f"(c[2]), "+f"(c[3])
        : "r"(a[0]), "r"(a[1]), "r"(a[2]), "r"(a[3]), "r"(b0), "r"(b1));
}

// A tile: 128 rows x 32 k halves (64B rows), 16B granules XORed by (row>>1)&3
__device__ __forceinline__ uint32_t a_addr(uint32_t base, int row, int kg) {
    return base + row * 64 + ((kg ^ ((row >> 1) & 3)) << 4);
}
// B tile: 32 k-rows x 256 n halves (512B rows), granule (0..31) XORed by (krow&7)
__device__ __forceinline__ uint32_t b_addr(uint32_t base, int krow, int g) {
    return base + krow * 512 + ((g ^ (krow & 7)) << 4);
}

#define A_BYTES     (128 * 64)            // 8 KB
#define B_BYTES     (32 * 512)            // 16 KB
#define STAGE_BYTES (A_BYTES + B_BYTES)   // 24 KB
#define NSTG        4
#define CONV_SMEM   (NSTG * STAGE_BYTES)  // 96 KB

// ---------------- weight reorder (tap-major, zero-padded, fp16) ----------------
__global__ void prep_weights(const float* __restrict__ w1, const float* __restrict__ w2,
                             const float* __restrict__ w3) {
    const int N1 = 128 * 160, N2 = 128 * 128, N3 = 384 * 1152;
    int i = blockIdx.x * blockDim.x + threadIdx.x;
    if (i < N1) {
        int oc = i / 160, k = i - oc * 160;
        int t = k >> 4, ch = k & 15;
        g_w1h[i] = __float2half((t < 9) ? w1[oc * 144 + ch * 9 + t] : 0.f);
    } else if (i < N1 + N2) {
        int j = i - N1;
        g_w2h[j] = __float2half(w2[j]);
    } else if (i < N1 + N2 + N3) {
        int j = i - N1 - N2;
        int oc = j / 1152, k = j - oc * 1152;
        int t = k >> 7, ch = k & 127;
        g_w3h[j] = __float2half((oc < OUTS) ? w3[oc * 1152 + ch * 9 + t] : 0.f);
    }
}

// ---------------- padded dw-replicated input builders ----------------
// Layout: P[dw][b][ch][r 0..65][w 0..63], P[...][r][w] = in[ch][r-1][w+dw-1] (0 if OOB)
__global__ void pad1_kernel(const float* __restrict__ x, const float* __restrict__ cond) {
    const int N = 3 * BB * 16 * 66 * 32;
    int i = blockIdx.x * blockDim.x + threadIdx.x;
    if (i >= N) return;
    int w2 = i & 31;           int tmp = i >> 5;
    int r  = tmp % 66;         tmp /= 66;
    int ch = tmp & 15;         tmp >>= 4;
    int b  = tmp & 31;         int dw = tmp >> 5;
    int rr = r - 1;
    const float* src = (ch < CC) ? (x    + ((size_t)b * CC    + ch)        * HW_)
                                 : (cond + ((size_t)b * CONDC + (ch - CC)) * HW_);
    float v0 = 0.f, v1 = 0.f;
    if ((unsigned)rr < 64u) {
        int w = w2 * 2;
        int ww0 = w + dw - 1, ww1 = ww0 + 1;
        if ((unsigned)ww0 < 64u) v0 = src[rr * 64 + ww0];
        if ((unsigned)ww1 < 64u) v1 = src[rr * 64 + ww1];
    }
    __half2* dst = reinterpret_cast<__half2*>(
        g_pad1 + (((size_t)(dw * BB + b) * 16 + ch) * PAREA) + r * 64);
    dst[w2] = __floats2half2_rn(v0, v1);
}

__global__ void pad3_kernel(const __half* __restrict__ h2) {
    const int N = 3 * BB * HID * 66 * 32;
    int i = blockIdx.x * blockDim.x + threadIdx.x;
    if (i >= N) return;
    int w2 = i & 31;           int tmp = i >> 5;
    int r  = tmp % 66;         tmp /= 66;
    int ch = tmp & 127;        tmp >>= 7;
    int b  = tmp & 31;         int dw = tmp >> 5;
    int rr = r - 1;
    const __half* src = h2 + ((size_t)b * HID + ch) * HW_;
    __half z = __ushort_as_half(0);
    __half v0 = z, v1 = z;
    if ((unsigned)rr < 64u) {
        int w = w2 * 2;
        int ww0 = w + dw - 1, ww1 = ww0 + 1;
        if ((unsigned)ww0 < 64u) v0 = src[rr * 64 + ww0];
        if ((unsigned)ww1 < 64u) v1 = src[rr * 64 + ww1];
    }
    __half2* dst = reinterpret_cast<__half2*>(
        g_pad3 + (((size_t)(dw * BB + b) * HID + ch) * PAREA) + r * 64);
    dst[w2] = __halves2half2(v0, v1);
}

// ---------------- fp16 multistage GEMM conv ----------------
// CTA: 256 threads (8 warps, 2(M) x 4(N)); tile M=128 x N=256 pixels (4 rows); BK=32.
// Both operands via cp.async (4-stage); A ldmatrix, B ldmatrix.trans from k-major tile.
template<bool PAD3, bool RELU, int COUT, int CIN, int CLOG, int KPAD, bool HALF_OUT>
__global__ __launch_bounds__(256, 1)
void conv_gemm(const __half* __restrict__ in, const __half* __restrict__ wgt,
               const float* __restrict__ bias, void* __restrict__ outp)
{
    constexpr int NC = KPAD / 32;
    extern __shared__ char smemc[];
    const uint32_t stg = smem_u32(smemc);

    const int tid  = threadIdx.x;
    const int lane = tid & 31;
    const int wid  = tid >> 5;
    const int wm   = (wid & 1) * 64;
    const int wn   = (wid >> 1) * 64;

    const int b     = blockIdx.z;
    const int mbase = blockIdx.y * 128;
    const int h0    = blockIdx.x * 4;
    const int pix0  = blockIdx.x * 256;

    // A-loader: 512 granules; thread covers gi = tid*2, tid*2+1
    const int a_row0 = (tid * 2) >> 2;
    const int a_kg0  = (tid * 2) & 3;
    // B-loader: krow = tid>>3; 4 granules, all within out-row orow
    const int b_krow = tid >> 3;
    const int b_orow = (tid & 7) >> 1;
    const int b_g0   = b_orow * 8 + (tid & 1) * 4;   // absolute granule base

    auto issue_stage = [&](int c) {
        if (c < NC) {
            const uint32_t sA = stg + (c & (NSTG - 1)) * STAGE_BYTES;
            const uint32_t sB = sA + A_BYTES;
            // A: weights [COUTPAD][KPAD]
            const __half* asrc = wgt + (size_t)(mbase + a_row0) * KPAD + c * 32 + a_kg0 * 8;
            cp_async16(a_addr(sA, a_row0, a_kg0), asrc);
            cp_async16(a_addr(sA, a_row0, a_kg0 + 1), asrc + 8);
            // B
            const int kk = c * 32 + b_krow;
            const __half* bsrc;
            if (PAD3) {
                int t9 = kk >> CLOG;
                if (t9 > 8) t9 = 8;                 // pad region: weights are zero
                const int ch = kk & (CIN - 1);
                const int dh = t9 / 3, dw = t9 - dh * 3;
                bsrc = in + (((size_t)(dw * BB + b) * CIN + ch) * PAREA)
                          + (size_t)(h0 + b_orow + dh) * 64 + (tid & 1) * 32;
            } else {
                bsrc = in + ((size_t)b * CIN + kk) * HW_ + pix0 + b_g0 * 8;
            }
            #pragma unroll
            for (int q = 0; q < 4; ++q)
                cp_async16(b_addr(sB, b_krow, b_g0 + q), bsrc + q * 8);
        }
        cp_commit();
    };

    float acc[4][8][4];
    #pragma unroll
    for (int mt = 0; mt < 4; ++mt)
        #pragma unroll
        for (int nt = 0; nt < 8; ++nt)
            #pragma unroll
            for (int q = 0; q < 4; ++q) acc[mt][nt][q] = 0.f;

    issue_stage(0);
    issue_stage(1);
    issue_stage(2);

    // ldmatrix lane bases
    const int a_m  = (lane & 7) + ((lane >> 3) & 1) * 8;   // + wm + mt*16
    const int a_kg = lane >> 4;                            // + 2*ks
    const int bl_k = ((lane >> 3) & 1) * 8 + (lane & 7);   // + 16*ks
    const int bl_g = lane >> 4;                            // + nt2*2 (granule)

    for (int c = 0; c < NC; ++c) {
        cp_wait2();
        __syncthreads();
        issue_stage(c + 3);

        const uint32_t sA = stg + (c & (NSTG - 1)) * STAGE_BYTES;
        const uint32_t sB = sA + A_BYTES;

        #pragma unroll
        for (int ks = 0; ks < 2; ++ks) {
            uint32_t af[4][4];
            #pragma unroll
            for (int mt = 0; mt < 4; ++mt)
                ldsm_x4(af[mt], a_addr(sA, wm + mt * 16 + a_m, 2 * ks + a_kg));
            #pragma unroll
            for (int nt2 = 0; nt2 < 4; ++nt2) {
                uint32_t bf[4];
                const int krow = 16 * ks + bl_k;
                const int g    = (wn >> 3) + nt2 * 2 + bl_g;
                ldsm_x4t(bf, b_addr(sB, krow, g));
                #pragma unroll
                for (int mt = 0; mt < 4; ++mt) {
                    mma_f16(acc[mt][nt2 * 2 + 0], af[mt], bf[0], bf[1]);
                    mma_f16(acc[mt][nt2 * 2 + 1], af[mt], bf[2], bf[3]);
                }
            }
        }
        __syncthreads();
    }

    // ---- epilogue ----
    const int g  = lane >> 2;
    const int tq = lane & 3;
    #pragma unroll
    for (int mt = 0; mt < 4; ++mt) {
        const int ocl = mbase + wm + mt * 16 + g;
        const int och = ocl + 8;
        const float bl = (ocl < COUT) ? bias[ocl] : 0.f;
        const float bh = (och < COUT) ? bias[och] : 0.f;
        #pragma unroll
        for (int nt = 0; nt < 8; ++nt) {
            const int col = wn + nt * 8 + 2 * tq;
            float v0 = acc[mt][nt][0] + bl, v1 = acc[mt][nt][1] + bl;
            float v2 = acc[mt][nt][2] + bh, v3 = acc[mt][nt][3] + bh;
            if (RELU) {
                v0 = fmaxf(v0, 0.f); v1 = fmaxf(v1, 0.f);
                v2 = fmaxf(v2, 0.f); v3 = fmaxf(v3, 0.f);
            }
            if constexpr (HALF_OUT) {
                __half* o = (__half*)outp;
                if (ocl < COUT)
                    *reinterpret_cast<__half2*>(o + ((size_t)b * COUT + ocl) * HW_ + pix0 + col) =
                        __floats2half2_rn(v0, v1);
                if (och < COUT)
                    *reinterpret_cast<__half2*>(o + ((size_t)b * COUT + och) * HW_ + pix0 + col) =
                        __floats2half2_rn(v2, v3);
            } else {
                float* o = (float*)outp;
                if (ocl < COUT)
                    *reinterpret_cast<float2*>(o + ((size_t)b * COUT + ocl) * HW_ + pix0 + col) =
                        make_float2(v0, v1);
                if (och < COUT)
                    *reinterpret_cast<float2*>(o + ((size_t)b * COUT + och) * HW_ + pix0 + col) =
                        make_float2(v2, v3);
            }
        }
    }
}

// ---------------- RQS pointwise transform (fast math) ----------------
__device__ __forceinline__ float softplusf(float v) {
    return (v > 20.f) ? v : __logf(1.f + __expf(v));
}

__global__ void rqs_kernel(const float* __restrict__ x, float* __restrict__ y)
{
    int i = blockIdx.x * blockDim.x + threadIdx.x;
    if (i >= NTOT) return;
    int hw = i & (HW_ - 1);
    int bc = i >> 12;          // b*CC + c
    int c = bc % CC;
    int b = bc / CC;
    const float* pp = g_params + (((size_t)b * OUTS + c * 23) * HW_) + hw;

    float xv = x[i];
    bool inside = (xv >= -TAILF) && (xv <= TAILF);
    float xin = fminf(fmaxf(xv, -TAILF), TAILF);

    float u[NB];
    float mx = -1e30f;
    #pragma unroll
    for (int j = 0; j < NB; ++j) { u[j] = pp[(size_t)j * HW_]; mx = fmaxf(mx, u[j]); }
    float se = 0.f;
    #pragma unroll
    for (int j = 0; j < NB; ++j) { u[j] = __expf(u[j] - mx); se += u[j]; }
    float inv = 1.f / se;
    float cw[NB + 1];
    cw[0] = -TAILF;
    float cs = 0.f;
    #pragma unroll
    for (int k = 0; k < NB; ++k) {
        cs += MBWF + (1.f - MBWF * NB) * (u[k] * inv);
        cw[k + 1] = 2.f * TAILF * cs - TAILF;
    }
    cw[NB] = TAILF;

    int t = 0;
    #pragma unroll
    for (int k = 1; k < NB; ++k) t += (xin >= cw[k]) ? 1 : 0;
    float in_cw = cw[t];
    float in_w  = cw[t + 1] - cw[t];

    mx = -1e30f;
    #pragma unroll
    for (int j = 0; j < NB; ++j) { u[j] = pp[(size_t)(NB + j) * HW_]; mx = fmaxf(mx, u[j]); }
    se = 0.f;
    #pragma unroll
    for (int j = 0; j < NB; ++j) { u[j] = __expf(u[j] - mx); se += u[j]; }
    inv = 1.f / se;
    float ch[NB + 1];
    ch[0] = -TAILF;
    cs = 0.f;
    #pragma unroll
    for (int k = 0; k < NB; ++k) {
        cs += MBHF + (1.f - MBHF * NB) * (u[k] * inv);
        ch[k + 1] = 2.f * TAILF * cs - TAILF;
    }
    ch[NB] = TAILF;
    float in_ch = ch[t];
    float in_h  = ch[t + 1] - ch[t];

    float d0 = 1.0f, d1 = 1.0f;
    if (t > 0)      d0 = MDF + softplusf(pp[(size_t)(2*NB + t - 1) * HW_]);
    if (t < NB - 1) d1 = MDF + softplusf(pp[(size_t)(2*NB + t) * HW_]);

    float delta = in_h / in_w;
    float th  = (xin - in_cw) / in_w;
    float tom = th * (1.f - th);
    float numer = in_h * (delta * th * th + d0 * tom);
    float denom = delta + (d0 + d1 - 2.f * delta) * tom;
    float yv = in_ch + numer / denom;
    float omt = 1.f - th;
    float dnum = delta * delta * (d1 * th * th + 2.f * delta * tom + d0 * omt * omt);
    float lad = __logf(dnum) - 2.f * __logf(denom);

    y[i] = inside ? yv : xv;
    g_lad[i] = inside ? lad : 0.f;
}

// ---------------- deterministic per-batch logdet reduction ----------------
__global__ void logdet_reduce(const float* __restrict__ logdet, float* __restrict__ out)
{
    int b = blockIdx.x;
    const float* p = g_lad + (size_t)b * PERB;
    double s = 0.0;
    for (int i = threadIdx.x; i < PERB; i += 256) s += (double)p[i];
    __shared__ double sm[256];
    sm[threadIdx.x] = s;
    __syncthreads();
    for (int st = 128; st > 0; st >>= 1) {
        if (threadIdx.x < st) sm[threadIdx.x] += sm[threadIdx.x + st];
        __syncthreads();
    }
    if (threadIdx.x == 0) out[b] = logdet[b] + (float)sm[0];
}

// ---------------- launch ----------------
extern "C" void kernel_launch(void* const* d_in, const int* in_sizes, int n_in,
                              void* d_out, int out_size)
{
    const float* x    = (const float*)d_in[0];
    const float* ld   = (const float*)d_in[1];
    const float* cond = (const float*)d_in[2];
    const float* w1   = (const float*)d_in[3];
    const float* b1   = (const float*)d_in[4];
    const float* w2   = (const float*)d_in[5];
    const float* b2   = (const float*)d_in[6];
    const float* w3   = (const float*)d_in[7];
    const float* b3   = (const float*)d_in[8];
    float* out = (float*)d_out;

    __half *p_pad1, *p_pad3, *p_h1, *p_w1, *p_w2, *p_w3;
    float *p_params;
    cudaGetSymbolAddress((void**)&p_pad1, g_pad1);
    cudaGetSymbolAddress((void**)&p_pad3, g_pad3);
    cudaGetSymbolAddress((void**)&p_h1, g_h1h);
    cudaGetSymbolAddress((void**)&p_w1, g_w1h);
    cudaGetSymbolAddress((void**)&p_w2, g_w2h);
    cudaGetSymbolAddress((void**)&p_w3, g_w3h);
    cudaGetSymbolAddress((void**)&p_params, g_params);

    // conv2 writes h2 into the pad3 buffer? No — it writes a temporary unpadded h2.
    // Reuse g_h1h for h2? h1 is consumed by conv2 before h2 is produced... they overlap
    // in time (conv2 reads h1, writes h2). Keep separate: alias h2 into g_pad3 tail is
    // unsafe; use a dedicated buffer: reuse g_params as fp16 h2? params written later.
    __half* p_h2 = reinterpret_cast<__half*>(p_params);  // 33MB fp16 inside 144MB region,
                                                         // consumed by pad3 before conv3
                                                         // overwrites params. Safe ordering.

    cudaFuncSetAttribute((const void*)conv_gemm<true,  true,  HID,  16,  4, 160,  true >,
                         cudaFuncAttributeMaxDynamicSharedMemorySize, CONV_SMEM);
    cudaFuncSetAttribute((const void*)conv_gemm<false, true,  HID,  128, 7, 128,  true >,
                         cudaFuncAttributeMaxDynamicSharedMemorySize, CONV_SMEM);
    cudaFuncSetAttribute((const void*)conv_gemm<true,  false, OUTS, 128, 7, 1152, false>,
                         cudaFuncAttributeMaxDynamicSharedMemorySize, CONV_SMEM);

    {
        const int NW = 128*160 + 128*128 + 384*1152;
        prep_weights<<<(NW + 255) / 256, 256>>>(w1, w2, w3);
    }
    {
        const int N = 3 * BB * 16 * 66 * 32;
        pad1_kernel<<<(N + 255) / 256, 256>>>(x, cond);
    }
    conv_gemm<true,  true,  HID, 16,  4, 160, true ><<<dim3(16, 1, BB), 256, CONV_SMEM>>>(p_pad1, p_w1, b1, p_h1);
    conv_gemm<false, true,  HID, 128, 7, 128, true ><<<dim3(16, 1, BB), 256, CONV_SMEM>>>(p_h1,   p_w2, b2, p_h2);
    {
        const int N = 3 * BB * HID * 66 * 32;
        pad3_kernel<<<(N + 255) / 256, 256>>>(p_h2);
    }
    conv_gemm<true,  false, OUTS, 128, 7, 1152, false><<<dim3(16, 3, BB), 256, CONV_SMEM>>>(p_pad3, p_w3, b3, p_params);
    rqs_kernel<<<(NTOT + 255) / 256, 256>>>(x, out);
    logdet_reduce<<<BB, 256>>>(ld, out + NTOT);
}

// round 8
// speedup vs baseline: 5.0402x; 1.0346x over previous
#include <cuda_runtime.h>
#include <cuda_fp16.h>
#include <math.h>
#include <cstdint>

// Problem constants
#define BB    32
#define CC    12
#define HH_   64
#define WW_   64
#define HW_   4096
#define HID   128
#define CONDC 4
#define OUTS  276          // 12 * 23
#define NB    8
#define TAILF 3.0f
#define MBWF  0.001f
#define MBHF  0.001f
#define MDF   0.001f
#define NTOT  (BB*CC*HW_)  // 1572864
#define PERB  (CC*HW_)     // 49152
#define PAREA (66*64)      // padded channel area (66 rows x 64 cols)
#define PBLK  192          // rqs partial-sum blocks per batch (PERB/256)

// ---------------- scratch (no cudaMalloc allowed) ----------------
__device__ __half g_pad1[(size_t)3*BB*16*PAREA];     // 13 MB
__device__ __half g_h1h[(size_t)BB*HID*HW_];          // 33 MB
__device__ __half g_pad3[(size_t)3*BB*HID*PAREA];    // 104 MB
__device__ __half g_w1h[128 * 160];
__device__ __half g_w2h[128 * 128];
__device__ __half g_w3h[384 * 1152];
__device__ float  g_params[(size_t)BB*OUTS*HW_];      // 144 MB
__device__ double g_psum[BB * PBLK];

// ---------------- helpers ----------------
__device__ __forceinline__ uint32_t smem_u32(const void* p) {
    uint32_t a;
    asm("{ .reg .u64 t; cvta.to.shared.u64 t, %1; cvt.u32.u64 %0, t; }" : "=r"(a) : "l"(p));
    return a;
}
__device__ __forceinline__ void cp_async16(uint32_t dst, const void* src) {
    asm volatile("cp.async.cg.shared.global [%0], [%1], 16;"
                 :: "r"(dst), "l"(src) : "memory");
}
__device__ __forceinline__ void cp_commit() {
    asm volatile("cp.async.commit_group;" ::: "memory");
}
template<int N>
__device__ __forceinline__ void cp_wait() {
    asm volatile("cp.async.wait_group %0;" :: "n"(N) : "memory");
}
__device__ __forceinline__ void ldsm_x4(uint32_t r[4], uint32_t addr) {
    asm volatile("ldmatrix.sync.aligned.m8n8.x4.shared.b16 {%0,%1,%2,%3}, [%4];"
        : "=r"(r[0]), "=r"(r[1]), "=r"(r[2]), "=r"(r[3]) : "r"(addr));
}
__device__ __forceinline__ void ldsm_x4t(uint32_t r[4], uint32_t addr) {
    asm volatile("ldmatrix.sync.aligned.m8n8.x4.trans.shared.b16 {%0,%1,%2,%3}, [%4];"
        : "=r"(r[0]), "=r"(r[1]), "=r"(r[2]), "=r"(r[3]) : "r"(addr));
}
__device__ __forceinline__ void mma_f16(float c[4], const uint32_t a[4],
                                        uint32_t b0, uint32_t b1) {
    asm volatile(
        "mma.sync.aligned.m16n8k16.row.col.f32.f16.f16.f32 "
        "{%0,%1,%2,%3}, {%4,%5,%6,%7}, {%8,%9}, {%0,%1,%2,%3};"
        : "+f"(c[0]), "+f"(c[1]), "+f"(c[2]), "+f"(c[3])
        : "r"(a[0]), "r"(a[1]), "r"(a[2]), "r"(a[3]), "r"(b0), "r"(b1));
}

// A tile: 128 rows x 32 k halves (64B rows), 16B granules XORed by (row>>1)&3
__device__ __forceinline__ uint32_t a_addr(uint32_t base, int row, int kg) {
    return base + row * 64 + ((kg ^ ((row >> 1) & 3)) << 4);
}
// B tile: 32 k-rows x 256 n halves (512B rows), granule (0..31) XORed by (krow&7)
__device__ __forceinline__ uint32_t b_addr(uint32_t base, int krow, int g) {
    return base + krow * 512 + ((g ^ (krow & 7)) << 4);
}

#define A_BYTES     (128 * 64)            // 8 KB
#define B_BYTES     (32 * 512)            // 16 KB
#define STAGE_BYTES (A_BYTES + B_BYTES)   // 24 KB
#define NSTG        6
#define CONV_SMEM   (NSTG * STAGE_BYTES)  // 144 KB

// ---------------- weight reorder (tap-major, zero-padded, fp16) ----------------
__global__ void prep_weights(const float* __restrict__ w1, const float* __restrict__ w2,
                             const float* __restrict__ w3) {
    const int N1 = 128 * 160, N2 = 128 * 128, N3 = 384 * 1152;
    int i = blockIdx.x * blockDim.x + threadIdx.x;
    if (i < N1) {
        int oc = i / 160, k = i - oc * 160;
        int t = k >> 4, ch = k & 15;
        g_w1h[i] = __float2half((t < 9) ? w1[oc * 144 + ch * 9 + t] : 0.f);
    } else if (i < N1 + N2) {
        int j = i - N1;
        g_w2h[j] = __float2half(w2[j]);
    } else if (i < N1 + N2 + N3) {
        int j = i - N1 - N2;
        int oc = j / 1152, k = j - oc * 1152;
        int t = k >> 7, ch = k & 127;
        g_w3h[j] = __float2half((oc < OUTS) ? w3[oc * 1152 + ch * 9 + t] : 0.f);
    }
}

// ---------------- padded dw-replicated input builders ----------------
// P[dw][b][ch][r 0..65][w 0..63] = in[ch][r-1][w+dw-1] (0 if OOB)
__global__ void pad1_kernel(const float* __restrict__ x, const float* __restrict__ cond) {
    const int N = 3 * BB * 16 * 66 * 32;
    int i = blockIdx.x * blockDim.x + threadIdx.x;
    if (i >= N) return;
    int w2 = i & 31;           int tmp = i >> 5;
    int r  = tmp % 66;         tmp /= 66;
    int ch = tmp & 15;         tmp >>= 4;
    int b  = tmp & 31;         int dw = tmp >> 5;
    int rr = r - 1;
    const float* src = (ch < CC) ? (x    + ((size_t)b * CC    + ch)        * HW_)
                                 : (cond + ((size_t)b * CONDC + (ch - CC)) * HW_);
    float v0 = 0.f, v1 = 0.f;
    if ((unsigned)rr < 64u) {
        int w = w2 * 2;
        int ww0 = w + dw - 1, ww1 = ww0 + 1;
        if ((unsigned)ww0 < 64u) v0 = src[rr * 64 + ww0];
        if ((unsigned)ww1 < 64u) v1 = src[rr * 64 + ww1];
    }
    __half2* dst = reinterpret_cast<__half2*>(
        g_pad1 + (((size_t)(dw * BB + b) * 16 + ch) * PAREA) + r * 64);
    dst[w2] = __floats2half2_rn(v0, v1);
}

__global__ void pad3_kernel(const __half* __restrict__ h2) {
    const int N = 3 * BB * HID * 66 * 32;
    int i = blockIdx.x * blockDim.x + threadIdx.x;
    if (i >= N) return;
    int w2 = i & 31;           int tmp = i >> 5;
    int r  = tmp % 66;         tmp /= 66;
    int ch = tmp & 127;        tmp >>= 7;
    int b  = tmp & 31;         int dw = tmp >> 5;
    int rr = r - 1;
    const __half* src = h2 + ((size_t)b * HID + ch) * HW_;
    __half z = __ushort_as_half(0);
    __half v0 = z, v1 = z;
    if ((unsigned)rr < 64u) {
        int w = w2 * 2;
        int ww0 = w + dw - 1, ww1 = ww0 + 1;
        if ((unsigned)ww0 < 64u) v0 = src[rr * 64 + ww0];
        if ((unsigned)ww1 < 64u) v1 = src[rr * 64 + ww1];
    }
    __half2* dst = reinterpret_cast<__half2*>(
        g_pad3 + (((size_t)(dw * BB + b) * HID + ch) * PAREA) + r * 64);
    dst[w2] = __halves2half2(v0, v1);
}

// ---------------- fp16 multistage GEMM conv ----------------
// CTA: 256 threads (8 warps, 2(M) x 4(N)); tile M=128 x N=256 pixels; BK=32; 6 stages.
template<bool PAD3, bool RELU, int COUT, int CIN, int CLOG, int KPAD, bool HALF_OUT>
__global__ __launch_bounds__(256, 1)
void conv_gemm(const __half* __restrict__ in, const __half* __restrict__ wgt,
               const float* __restrict__ bias, void* __restrict__ outp)
{
    constexpr int NC = KPAD / 32;
    extern __shared__ char smemc[];
    const uint32_t stg = smem_u32(smemc);

    const int tid  = threadIdx.x;
    const int lane = tid & 31;
    const int wid  = tid >> 5;
    const int wm   = (wid & 1) * 64;
    const int wn   = (wid >> 1) * 64;

    const int b     = blockIdx.z;
    const int mbase = blockIdx.y * 128;
    const int h0    = blockIdx.x * 4;
    const int pix0  = blockIdx.x * 256;

    const int a_row0 = (tid * 2) >> 2;
    const int a_kg0  = (tid * 2) & 3;
    const int b_krow = tid >> 3;
    const int b_orow = (tid & 7) >> 1;
    const int b_g0   = b_orow * 8 + (tid & 1) * 4;

    auto stage_idx = [](int c) { return (c % NSTG); };

    auto issue_stage = [&](int c) {
        if (c < NC) {
            const uint32_t sA = stg + stage_idx(c) * STAGE_BYTES;
            const uint32_t sB = sA + A_BYTES;
            const __half* asrc = wgt + (size_t)(mbase + a_row0) * KPAD + c * 32 + a_kg0 * 8;
            cp_async16(a_addr(sA, a_row0, a_kg0), asrc);
            cp_async16(a_addr(sA, a_row0, a_kg0 + 1), asrc + 8);
            const int kk = c * 32 + b_krow;
            const __half* bsrc;
            if (PAD3) {
                int t9 = kk >> CLOG;
                if (t9 > 8) t9 = 8;                 // pad region: weights are zero
                const int ch = kk & (CIN - 1);
                const int dh = t9 / 3, dw = t9 - dh * 3;
                bsrc = in + (((size_t)(dw * BB + b) * CIN + ch) * PAREA)
                          + (size_t)(h0 + b_orow + dh) * 64 + (tid & 1) * 32;
            } else {
                bsrc = in + ((size_t)b * CIN + kk) * HW_ + pix0 + b_g0 * 8;
            }
            #pragma unroll
            for (int q = 0; q < 4; ++q)
                cp_async16(b_addr(sB, b_krow, b_g0 + q), bsrc + q * 8);
        }
        cp_commit();
    };

    float acc[4][8][4];
    #pragma unroll
    for (int mt = 0; mt < 4; ++mt)
        #pragma unroll
        for (int nt = 0; nt < 8; ++nt)
            #pragma unroll
            for (int q = 0; q < 4; ++q) acc[mt][nt][q] = 0.f;

    #pragma unroll
    for (int s = 0; s < NSTG - 1; ++s) issue_stage(s);

    // ldmatrix lane bases
    const int a_m  = (lane & 7) + ((lane >> 3) & 1) * 8;
    const int a_kg = lane >> 4;
    const int bl_k = ((lane >> 3) & 1) * 8 + (lane & 7);
    const int bl_g = lane >> 4;

    for (int c = 0; c < NC; ++c) {
        cp_wait<NSTG - 2>();
        __syncthreads();
        issue_stage(c + NSTG - 1);

        const uint32_t sA = stg + stage_idx(c) * STAGE_BYTES;
        const uint32_t sB = sA + A_BYTES;

        #pragma unroll
        for (int ks = 0; ks < 2; ++ks) {
            uint32_t af[4][4];
            uint32_t bf[4][4];
            #pragma unroll
            for (int mt = 0; mt < 4; ++mt)
                ldsm_x4(af[mt], a_addr(sA, wm + mt * 16 + a_m, 2 * ks + a_kg));
            #pragma unroll
            for (int nt2 = 0; nt2 < 4; ++nt2)
                ldsm_x4t(bf[nt2], b_addr(sB, 16 * ks + bl_k, (wn >> 3) + nt2 * 2 + bl_g));
            #pragma unroll
            for (int nt2 = 0; nt2 < 4; ++nt2) {
                #pragma unroll
                for (int mt = 0; mt < 4; ++mt) {
                    mma_f16(acc[mt][nt2 * 2 + 0], af[mt], bf[nt2][0], bf[nt2][1]);
                    mma_f16(acc[mt][nt2 * 2 + 1], af[mt], bf[nt2][2], bf[nt2][3]);
                }
            }
        }
        // no trailing barrier: next iteration's leading barrier (after cp_wait)
        // orders all reads of this stage before any overwrite of buffer (c-1)%NSTG.
    }

    // ---- epilogue ----
    const int g  = lane >> 2;
    const int tq = lane & 3;
    #pragma unroll
    for (int mt = 0; mt < 4; ++mt) {
        const int ocl = mbase + wm + mt * 16 + g;
        const int och = ocl + 8;
        const float bl = (ocl < COUT) ? bias[ocl] : 0.f;
        const float bh = (och < COUT) ? bias[och] : 0.f;
        #pragma unroll
        for (int nt = 0; nt < 8; ++nt) {
            const int col = wn + nt * 8 + 2 * tq;
            float v0 = acc[mt][nt][0] + bl, v1 = acc[mt][nt][1] + bl;
            float v2 = acc[mt][nt][2] + bh, v3 = acc[mt][nt][3] + bh;
            if (RELU) {
                v0 = fmaxf(v0, 0.f); v1 = fmaxf(v1, 0.f);
                v2 = fmaxf(v2, 0.f); v3 = fmaxf(v3, 0.f);
            }
            if constexpr (HALF_OUT) {
                __half* o = (__half*)outp;
                if (ocl < COUT)
                    *reinterpret_cast<__half2*>(o + ((size_t)b * COUT + ocl) * HW_ + pix0 + col) =
                        __floats2half2_rn(v0, v1);
                if (och < COUT)
                    *reinterpret_cast<__half2*>(o + ((size_t)b * COUT + och) * HW_ + pix0 + col) =
                        __floats2half2_rn(v2, v3);
            } else {
                float* o = (float*)outp;
                if (ocl < COUT)
                    *reinterpret_cast<float2*>(o + ((size_t)b * COUT + ocl) * HW_ + pix0 + col) =
                        make_float2(v0, v1);
                if (och < COUT)
                    *reinterpret_cast<float2*>(o + ((size_t)b * COUT + och) * HW_ + pix0 + col) =
                        make_float2(v2, v3);
            }
        }
    }
}

// ---------------- RQS pointwise transform + fused partial logdet ----------------
__device__ __forceinline__ float softplusf(float v) {
    return (v > 20.f) ? v : __logf(1.f + __expf(v));
}

__global__ void rqs_kernel(const float* __restrict__ x, float* __restrict__ y)
{
    const int b   = blockIdx.y;
    const int blk = blockIdx.x;                       // 0..PBLK-1
    const int i   = b * PERB + blk * 256 + threadIdx.x;
    const int hw  = i & (HW_ - 1);
    const int c   = (i >> 12) % CC;
    const float* pp = g_params + (((size_t)b * OUTS + c * 23) * HW_) + hw;

    float xv = x[i];
    bool inside = (xv >= -TAILF) && (xv <= TAILF);
    float xin = fminf(fmaxf(xv, -TAILF), TAILF);

    float u[NB];
    float mx = -1e30f;
    #pragma unroll
    for (int j = 0; j < NB; ++j) { u[j] = pp[(size_t)j * HW_]; mx = fmaxf(mx, u[j]); }
    float se = 0.f;
    #pragma unroll
    for (int j = 0; j < NB; ++j) { u[j] = __expf(u[j] - mx); se += u[j]; }
    float inv = 1.f / se;
    float cw[NB + 1];
    cw[0] = -TAILF;
    float cs = 0.f;
    #pragma unroll
    for (int k = 0; k < NB; ++k) {
        cs += MBWF + (1.f - MBWF * NB) * (u[k] * inv);
        cw[k + 1] = 2.f * TAILF * cs - TAILF;
    }
    cw[NB] = TAILF;

    int t = 0;
    #pragma unroll
    for (int k = 1; k < NB; ++k) t += (xin >= cw[k]) ? 1 : 0;
    float in_cw = cw[t];
    float in_w  = cw[t + 1] - cw[t];

    mx = -1e30f;
    #pragma unroll
    for (int j = 0; j < NB; ++j) { u[j] = pp[(size_t)(NB + j) * HW_]; mx = fmaxf(mx, u[j]); }
    se = 0.f;
    #pragma unroll
    for (int j = 0; j < NB; ++j) { u[j] = __expf(u[j] - mx); se += u[j]; }
    inv = 1.f / se;
    float ch[NB + 1];
    ch[0] = -TAILF;
    cs = 0.f;
    #pragma unroll
    for (int k = 0; k < NB; ++k) {
        cs += MBHF + (1.f - MBHF * NB) * (u[k] * inv);
        ch[k + 1] = 2.f * TAILF * cs - TAILF;
    }
    ch[NB] = TAILF;
    float in_ch = ch[t];
    float in_h  = ch[t + 1] - ch[t];

    float d0 = 1.0f, d1 = 1.0f;
    if (t > 0)      d0 = MDF + softplusf(pp[(size_t)(2*NB + t - 1) * HW_]);
    if (t < NB - 1) d1 = MDF + softplusf(pp[(size_t)(2*NB + t) * HW_]);

    float delta = in_h / in_w;
    float th  = (xin - in_cw) / in_w;
    float tom = th * (1.f - th);
    float numer = in_h * (delta * th * th + d0 * tom);
    float denom = delta + (d0 + d1 - 2.f * delta) * tom;
    float yv = in_ch + numer / denom;
    float omt = 1.f - th;
    float dnum = delta * delta * (d1 * th * th + 2.f * delta * tom + d0 * omt * omt);
    float lad = __logf(dnum) - 2.f * __logf(denom);

    y[i] = inside ? yv : xv;

    // fused deterministic block partial sum of lad
    __shared__ double sm[256];
    sm[threadIdx.x] = inside ? (double)lad : 0.0;
    __syncthreads();
    for (int st = 128; st > 0; st >>= 1) {
        if (threadIdx.x < st) sm[threadIdx.x] += sm[threadIdx.x + st];
        __syncthreads();
    }
    if (threadIdx.x == 0) g_psum[b * PBLK + blk] = sm[0];
}

__global__ void logdet_reduce(const float* __restrict__ logdet, float* __restrict__ out)
{
    int b = blockIdx.x;
    double s = (threadIdx.x < PBLK) ? g_psum[b * PBLK + threadIdx.x] : 0.0;
    __shared__ double sm[256];
    sm[threadIdx.x] = s;
    __syncthreads();
    for (int st = 128; st > 0; st >>= 1) {
        if (threadIdx.x < st) sm[threadIdx.x] += sm[threadIdx.x + st];
        __syncthreads();
    }
    if (threadIdx.x == 0) out[b] = logdet[b] + (float)sm[0];
}

// ---------------- launch ----------------
extern "C" void kernel_launch(void* const* d_in, const int* in_sizes, int n_in,
                              void* d_out, int out_size)
{
    const float* x    = (const float*)d_in[0];
    const float* ld   = (const float*)d_in[1];
    const float* cond = (const float*)d_in[2];
    const float* w1   = (const float*)d_in[3];
    const float* b1   = (const float*)d_in[4];
    const float* w2   = (const float*)d_in[5];
    const float* b2   = (const float*)d_in[6];
    const float* w3   = (const float*)d_in[7];
    const float* b3   = (const float*)d_in[8];
    float* out = (float*)d_out;

    __half *p_pad1, *p_pad3, *p_h1, *p_w1, *p_w2, *p_w3;
    float *p_params;
    cudaGetSymbolAddress((void**)&p_pad1, g_pad1);
    cudaGetSymbolAddress((void**)&p_pad3, g_pad3);
    cudaGetSymbolAddress((void**)&p_h1, g_h1h);
    cudaGetSymbolAddress((void**)&p_w1, g_w1h);
    cudaGetSymbolAddress((void**)&p_w2, g_w2h);
    cudaGetSymbolAddress((void**)&p_w3, g_w3h);
    cudaGetSymbolAddress((void**)&p_params, g_params);

    // h2 (fp16, 33MB) aliases the head of g_params (144MB): consumed by pad3
    // strictly before conv3 writes params. Safe ordering on one stream.
    __half* p_h2 = reinterpret_cast<__half*>(p_params);

    cudaFuncSetAttribute((const void*)conv_gemm<true,  true,  HID,  16,  4, 160,  true >,
                         cudaFuncAttributeMaxDynamicSharedMemorySize, CONV_SMEM);
    cudaFuncSetAttribute((const void*)conv_gemm<false, true,  HID,  128, 7, 128,  true >,
                         cudaFuncAttributeMaxDynamicSharedMemorySize, CONV_SMEM);
    cudaFuncSetAttribute((const void*)conv_gemm<true,  false, OUTS, 128, 7, 1152, false>,
                         cudaFuncAttributeMaxDynamicSharedMemorySize, CONV_SMEM);

    {
        const int NW = 128*160 + 128*128 + 384*1152;
        prep_weights<<<(NW + 255) / 256, 256>>>(w1, w2, w3);
    }
    {
        const int N = 3 * BB * 16 * 66 * 32;
        pad1_kernel<<<(N + 255) / 256, 256>>>(x, cond);
    }
    conv_gemm<true,  true,  HID, 16,  4, 160, true ><<<dim3(16, 1, BB), 256, CONV_SMEM>>>(p_pad1, p_w1, b1, p_h1);
    conv_gemm<false, true,  HID, 128, 7, 128, true ><<<dim3(16, 1, BB), 256, CONV_SMEM>>>(p_h1,   p_w2, b2, p_h2);
    {
        const int N = 3 * BB * HID * 66 * 32;
        pad3_kernel<<<(N + 255) / 256, 256>>>(p_h2);
    }
    conv_gemm<true,  false, OUTS, 128, 7, 1152, false><<<dim3(16, 3, BB), 256, CONV_SMEM>>>(p_pad3, p_w3, b3, p_params);
    rqs_kernel<<<dim3(PBLK, BB), 256>>>(x, out);
    logdet_reduce<<<BB, 256>>>(ld, out + NTOT);
}

// round 9
// speedup vs baseline: 6.1498x; 1.2202x over previous
#include <cuda_runtime.h>
#include <cuda_fp16.h>
#include <math.h>
#include <cstdint>

// Problem constants
#define BB    32
#define CC    12
#define HH_   64
#define WW_   64
#define HW_   4096
#define HID   128
#define CONDC 4
#define OUTS  276          // 12 * 23
#define NB    8
#define TAILF 3.0f
#define MBWF  0.001f
#define MBHF  0.001f
#define MDF   0.001f
#define NTOT  (BB*CC*HW_)  // 1572864
#define PERB  (CC*HW_)     // 49152
#define PAREA (66*64)      // padded channel area (66 rows x 64 cols)
#define PBLK  192          // rqs partial-sum blocks per batch (PERB/256)

// ---------------- scratch (no cudaMalloc allowed) ----------------
__device__ __half g_pad1[(size_t)3*BB*16*PAREA];     // 13 MB
__device__ __half g_h1h[(size_t)BB*HID*HW_];          // 33 MB
__device__ __half g_pad3[(size_t)3*BB*HID*PAREA];    // 104 MB
__device__ __half g_w1h[128 * 160];
__device__ __half g_w2h[128 * 128];
__device__ __half g_w3h[384 * 1152];
__device__ float  g_params[(size_t)BB*OUTS*HW_];      // 144 MB
__device__ double g_psum[BB * PBLK];

// ---------------- helpers ----------------
__device__ __forceinline__ uint32_t smem_u32(const void* p) {
    uint32_t a;
    asm("{ .reg .u64 t; cvta.to.shared.u64 t, %1; cvt.u32.u64 %0, t; }" : "=r"(a) : "l"(p));
    return a;
}
__device__ __forceinline__ void cp_async16(uint32_t dst, const void* src) {
    asm volatile("cp.async.cg.shared.global [%0], [%1], 16;"
                 :: "r"(dst), "l"(src) : "memory");
}
__device__ __forceinline__ void cp_commit() {
    asm volatile("cp.async.commit_group;" ::: "memory");
}
template<int N>
__device__ __forceinline__ void cp_wait() {
    asm volatile("cp.async.wait_group %0;" :: "n"(N) : "memory");
}
__device__ __forceinline__ void ldsm_x4(uint32_t r[4], uint32_t addr) {
    asm volatile("ldmatrix.sync.aligned.m8n8.x4.shared.b16 {%0,%1,%2,%3}, [%4];"
        : "=r"(r[0]), "=r"(r[1]), "=r"(r[2]), "=r"(r[3]) : "r"(addr));
}
__device__ __forceinline__ void ldsm_x4t(uint32_t r[4], uint32_t addr) {
    asm volatile("ldmatrix.sync.aligned.m8n8.x4.trans.shared.b16 {%0,%1,%2,%3}, [%4];"
        : "=r"(r[0]), "=r"(r[1]), "=r"(r[2]), "=r"(r[3]) : "r"(addr));
}
__device__ __forceinline__ void mma_f16(float c[4], const uint32_t a[4],
                                        uint32_t b0, uint32_t b1) {
    asm volatile(
        "mma.sync.aligned.m16n8k16.row.col.f32.f16.f16.f32 "
        "{%0,%1,%2,%3}, {%4,%5,%6,%7}, {%8,%9}, {%0,%1,%2,%3};"
        : "+f"(c[0]), "+f"(c[1]), "+f"(c[2]), "+f"(c[3])
        : "r"(a[0]), "r"(a[1]), "r"(a[2]), "r"(a[3]), "r"(b0), "r"(b1));
}

// A tile: 128 rows x 32 k halves (64B rows), 16B granules XORed by (row>>1)&3
__device__ __forceinline__ uint32_t a_addr(uint32_t base, int row, int kg) {
    return base + row * 64 + ((kg ^ ((row >> 1) & 3)) << 4);
}
// B tile: 32 k-rows x 128 n halves (256B rows, 16 granules), granule XORed by (krow&7)
__device__ __forceinline__ uint32_t b_addr(uint32_t base, int krow, int g) {
    return base + krow * 256 + ((g ^ (krow & 7)) << 4);
}

#define A_BYTES     (128 * 64)            // 8 KB
#define B_BYTES     (32 * 256)            // 8 KB
#define STAGE_BYTES (A_BYTES + B_BYTES)   // 16 KB
#define NSTG        6
#define CONV_SMEM   (NSTG * STAGE_BYTES)  // 96 KB -> 2 CTAs/SM

// ---------------- weight reorder (tap-major, zero-padded, fp16) ----------------
__global__ void prep_weights(const float* __restrict__ w1, const float* __restrict__ w2,
                             const float* __restrict__ w3) {
    const int N1 = 128 * 160, N2 = 128 * 128, N3 = 384 * 1152;
    int i = blockIdx.x * blockDim.x + threadIdx.x;
    if (i < N1) {
        int oc = i / 160, k = i - oc * 160;
        int t = k >> 4, ch = k & 15;
        g_w1h[i] = __float2half((t < 9) ? w1[oc * 144 + ch * 9 + t] : 0.f);
    } else if (i < N1 + N2) {
        int j = i - N1;
        g_w2h[j] = __float2half(w2[j]);
    } else if (i < N1 + N2 + N3) {
        int j = i - N1 - N2;
        int oc = j / 1152, k = j - oc * 1152;
        int t = k >> 7, ch = k & 127;
        g_w3h[j] = __float2half((oc < OUTS) ? w3[oc * 1152 + ch * 9 + t] : 0.f);
    }
}

// ---------------- padded dw-replicated input builders ----------------
// P[dw][b][ch][r 0..65][w 0..63] = in[ch][r-1][w+dw-1] (0 if OOB)
__global__ void pad1_kernel(const float* __restrict__ x, const float* __restrict__ cond) {
    const int N = 3 * BB * 16 * 66 * 32;
    int i = blockIdx.x * blockDim.x + threadIdx.x;
    if (i >= N) return;
    int w2 = i & 31;           int tmp = i >> 5;
    int r  = tmp % 66;         tmp /= 66;
    int ch = tmp & 15;         tmp >>= 4;
    int b  = tmp & 31;         int dw = tmp >> 5;
    int rr = r - 1;
    const float* src = (ch < CC) ? (x    + ((size_t)b * CC    + ch)        * HW_)
                                 : (cond + ((size_t)b * CONDC + (ch - CC)) * HW_);
    float v0 = 0.f, v1 = 0.f;
    if ((unsigned)rr < 64u) {
        int w = w2 * 2;
        int ww0 = w + dw - 1, ww1 = ww0 + 1;
        if ((unsigned)ww0 < 64u) v0 = src[rr * 64 + ww0];
        if ((unsigned)ww1 < 64u) v1 = src[rr * 64 + ww1];
    }
    __half2* dst = reinterpret_cast<__half2*>(
        g_pad1 + (((size_t)(dw * BB + b) * 16 + ch) * PAREA) + r * 64);
    dst[w2] = __floats2half2_rn(v0, v1);
}

__global__ void pad3_kernel(const __half* __restrict__ h2) {
    const int N = 3 * BB * HID * 66 * 32;
    int i = blockIdx.x * blockDim.x + threadIdx.x;
    if (i >= N) return;
    int w2 = i & 31;           int tmp = i >> 5;
    int r  = tmp % 66;         tmp /= 66;
    int ch = tmp & 127;        tmp >>= 7;
    int b  = tmp & 31;         int dw = tmp >> 5;
    int rr = r - 1;
    const __half* src = h2 + ((size_t)b * HID + ch) * HW_;
    __half z = __ushort_as_half(0);
    __half v0 = z, v1 = z;
    if ((unsigned)rr < 64u) {
        int w = w2 * 2;
        int ww0 = w + dw - 1, ww1 = ww0 + 1;
        if ((unsigned)ww0 < 64u) v0 = src[rr * 64 + ww0];
        if ((unsigned)ww1 < 64u) v1 = src[rr * 64 + ww1];
    }
    __half2* dst = reinterpret_cast<__half2*>(
        g_pad3 + (((size_t)(dw * BB + b) * HID + ch) * PAREA) + r * 64);
    dst[w2] = __halves2half2(v0, v1);
}

// ---------------- fp16 multistage GEMM conv (2 CTAs/SM) ----------------
// CTA: 256 threads (8 warps, 4(M) x 2(N)); tile M=128 x N=128 pixels (2 rows); BK=32.
// Warp tile 32x64: acc = 64 regs/thread -> 2 CTAs resident.
template<bool PAD3, bool RELU, int COUT, int CIN, int CLOG, int KPAD, bool HALF_OUT>
__global__ __launch_bounds__(256, 2)
void conv_gemm(const __half* __restrict__ in, const __half* __restrict__ wgt,
               const float* __restrict__ bias, void* __restrict__ outp)
{
    constexpr int NC = KPAD / 32;
    extern __shared__ char smemc[];
    const uint32_t stg = smem_u32(smemc);

    const int tid  = threadIdx.x;
    const int lane = tid & 31;
    const int wid  = tid >> 5;
    const int wm   = (wid & 3) * 32;
    const int wn   = (wid >> 2) * 64;

    const int b     = blockIdx.z;
    const int mbase = blockIdx.y * 128;
    const int h0    = blockIdx.x * 2;
    const int pix0  = blockIdx.x * 128;

    // A-loader: 512 granules, 2/thread (32B contiguous)
    const int a_row0 = tid >> 1;
    const int a_kg0  = (tid & 1) * 2;
    // B-loader: 256 granule-pairs; krow = tid>>3, granules g0, g0+1 (32B contiguous)
    const int b_krow = tid >> 3;
    const int b_g0   = (tid & 7) * 2;
    const int b_orow = b_g0 >> 3;       // 0 or 1 (which of the 2 image rows)

    auto issue_stage = [&](int c) {
        if (c < NC) {
            const uint32_t sA = stg + (c % NSTG) * STAGE_BYTES;
            const uint32_t sB = sA + A_BYTES;
            const __half* asrc = wgt + (size_t)(mbase + a_row0) * KPAD + c * 32 + a_kg0 * 8;
            cp_async16(a_addr(sA, a_row0, a_kg0), asrc);
            cp_async16(a_addr(sA, a_row0, a_kg0 + 1), asrc + 8);
            const int kk = c * 32 + b_krow;
            const __half* bsrc;
            if (PAD3) {
                int t9 = kk >> CLOG;
                if (t9 > 8) t9 = 8;                 // pad region: weights are zero
                const int ch = kk & (CIN - 1);
                const int dh = t9 / 3, dw = t9 - dh * 3;
                bsrc = in + (((size_t)(dw * BB + b) * CIN + ch) * PAREA)
                          + (size_t)(h0 + b_orow + dh) * 64 + (b_g0 & 7) * 8;
            } else {
                bsrc = in + ((size_t)b * CIN + kk) * HW_ + pix0 + b_g0 * 8;
            }
            cp_async16(b_addr(sB, b_krow, b_g0), bsrc);
            cp_async16(b_addr(sB, b_krow, b_g0 + 1), bsrc + 8);
        }
        cp_commit();
    };

    float acc[2][8][4];
    #pragma unroll
    for (int mt = 0; mt < 2; ++mt)
        #pragma unroll
        for (int nt = 0; nt < 8; ++nt)
            #pragma unroll
            for (int q = 0; q < 4; ++q) acc[mt][nt][q] = 0.f;

    #pragma unroll
    for (int s = 0; s < NSTG - 1; ++s) issue_stage(s);

    // ldmatrix lane bases
    const int a_m  = (lane & 7) + ((lane >> 3) & 1) * 8;
    const int a_kg = lane >> 4;
    const int bl_k = ((lane >> 3) & 1) * 8 + (lane & 7);
    const int bl_g = lane >> 4;

    for (int c = 0; c < NC; ++c) {
        cp_wait<NSTG - 2>();
        __syncthreads();
        issue_stage(c + NSTG - 1);

        const uint32_t sA = stg + (c % NSTG) * STAGE_BYTES;
        const uint32_t sB = sA + A_BYTES;

        #pragma unroll
        for (int ks = 0; ks < 2; ++ks) {
            uint32_t af[2][4];
            uint32_t bf[4][4];
            #pragma unroll
            for (int mt = 0; mt < 2; ++mt)
                ldsm_x4(af[mt], a_addr(sA, wm + mt * 16 + a_m, 2 * ks + a_kg));
            #pragma unroll
            for (int nt2 = 0; nt2 < 4; ++nt2)
                ldsm_x4t(bf[nt2], b_addr(sB, 16 * ks + bl_k, (wn >> 3) + nt2 * 2 + bl_g));
            #pragma unroll
            for (int nt2 = 0; nt2 < 4; ++nt2) {
                #pragma unroll
                for (int mt = 0; mt < 2; ++mt) {
                    mma_f16(acc[mt][nt2 * 2 + 0], af[mt], bf[nt2][0], bf[nt2][1]);
                    mma_f16(acc[mt][nt2 * 2 + 1], af[mt], bf[nt2][2], bf[nt2][3]);
                }
            }
        }
        // no trailing barrier: next iteration's leading barrier (after cp_wait)
        // orders all reads of this stage before any overwrite.
    }

    // ---- epilogue ----
    const int g  = lane >> 2;
    const int tq = lane & 3;
    #pragma unroll
    for (int mt = 0; mt < 2; ++mt) {
        const int ocl = mbase + wm + mt * 16 + g;
        const int och = ocl + 8;
        const float bl = (ocl < COUT) ? bias[ocl] : 0.f;
        const float bh = (och < COUT) ? bias[och] : 0.f;
        #pragma unroll
        for (int nt = 0; nt < 8; ++nt) {
            const int col = wn + nt * 8 + 2 * tq;
            float v0 = acc[mt][nt][0] + bl, v1 = acc[mt][nt][1] + bl;
            float v2 = acc[mt][nt][2] + bh, v3 = acc[mt][nt][3] + bh;
            if (RELU) {
                v0 = fmaxf(v0, 0.f); v1 = fmaxf(v1, 0.f);
                v2 = fmaxf(v2, 0.f); v3 = fmaxf(v3, 0.f);
            }
            if constexpr (HALF_OUT) {
                __half* o = (__half*)outp;
                if (ocl < COUT)
                    *reinterpret_cast<__half2*>(o + ((size_t)b * COUT + ocl) * HW_ + pix0 + col) =
                        __floats2half2_rn(v0, v1);
                if (och < COUT)
                    *reinterpret_cast<__half2*>(o + ((size_t)b * COUT + och) * HW_ + pix0 + col) =
                        __floats2half2_rn(v2, v3);
            } else {
                float* o = (float*)outp;
                if (ocl < COUT)
                    *reinterpret_cast<float2*>(o + ((size_t)b * COUT + ocl) * HW_ + pix0 + col) =
                        make_float2(v0, v1);
                if (och < COUT)
                    *reinterpret_cast<float2*>(o + ((size_t)b * COUT + och) * HW_ + pix0 + col) =
                        make_float2(v2, v3);
            }
        }
    }
}

// ---------------- RQS pointwise transform + fused partial logdet ----------------
__device__ __forceinline__ float softplusf(float v) {
    return (v > 20.f) ? v : __logf(1.f + __expf(v));
}

__global__ void rqs_kernel(const float* __restrict__ x, float* __restrict__ y)
{
    const int b   = blockIdx.y;
    const int blk = blockIdx.x;                       // 0..PBLK-1
    const int i   = b * PERB + blk * 256 + threadIdx.x;
    const int hw  = i & (HW_ - 1);
    const int c   = (i >> 12) % CC;
    const float* pp = g_params + (((size_t)b * OUTS + c * 23) * HW_) + hw;

    float xv = x[i];
    bool inside = (xv >= -TAILF) && (xv <= TAILF);
    float xin = fminf(fmaxf(xv, -TAILF), TAILF);

    float u[NB];
    float mx = -1e30f;
    #pragma unroll
    for (int j = 0; j < NB; ++j) { u[j] = pp[(size_t)j * HW_]; mx = fmaxf(mx, u[j]); }
    float se = 0.f;
    #pragma unroll
    for (int j = 0; j < NB; ++j) { u[j] = __expf(u[j] - mx); se += u[j]; }
    float inv = 1.f / se;
    float cw[NB + 1];
    cw[0] = -TAILF;
    float cs = 0.f;
    #pragma unroll
    for (int k = 0; k < NB; ++k) {
        cs += MBWF + (1.f - MBWF * NB) * (u[k] * inv);
        cw[k + 1] = 2.f * TAILF * cs - TAILF;
    }
    cw[NB] = TAILF;

    int t = 0;
    #pragma unroll
    for (int k = 1; k < NB; ++k) t += (xin >= cw[k]) ? 1 : 0;
    float in_cw = cw[t];
    float in_w  = cw[t + 1] - cw[t];

    mx = -1e30f;
    #pragma unroll
    for (int j = 0; j < NB; ++j) { u[j] = pp[(size_t)(NB + j) * HW_]; mx = fmaxf(mx, u[j]); }
    se = 0.f;
    #pragma unroll
    for (int j = 0; j < NB; ++j) { u[j] = __expf(u[j] - mx); se += u[j]; }
    inv = 1.f / se;
    float ch[NB + 1];
    ch[0] = -TAILF;
    cs = 0.f;
    #pragma unroll
    for (int k = 0; k < NB; ++k) {
        cs += MBHF + (1.f - MBHF * NB) * (u[k] * inv);
        ch[k + 1] = 2.f * TAILF * cs - TAILF;
    }
    ch[NB] = TAILF;
    float in_ch = ch[t];
    float in_h  = ch[t + 1] - ch[t];

    float d0 = 1.0f, d1 = 1.0f;
    if (t > 0)      d0 = MDF + softplusf(pp[(size_t)(2*NB + t - 1) * HW_]);
    if (t < NB - 1) d1 = MDF + softplusf(pp[(size_t)(2*NB + t) * HW_]);

    float delta = in_h / in_w;
    float th  = (xin - in_cw) / in_w;
    float tom = th * (1.f - th);
    float numer = in_h * (delta * th * th + d0 * tom);
    float denom = delta + (d0 + d1 - 2.f * delta) * tom;
    float yv = in_ch + numer / denom;
    float omt = 1.f - th;
    float dnum = delta * delta * (d1 * th * th + 2.f * delta * tom + d0 * omt * omt);
    float lad = __logf(dnum) - 2.f * __logf(denom);

    y[i] = inside ? yv : xv;

    // fused deterministic block partial sum of lad
    __shared__ double sm[256];
    sm[threadIdx.x] = inside ? (double)lad : 0.0;
    __syncthreads();
    for (int st = 128; st > 0; st >>= 1) {
        if (threadIdx.x < st) sm[threadIdx.x] += sm[threadIdx.x + st];
        __syncthreads();
    }
    if (threadIdx.x == 0) g_psum[b * PBLK + blk] = sm[0];
}

__global__ void logdet_reduce(const float* __restrict__ logdet, float* __restrict__ out)
{
    int b = blockIdx.x;
    double s = (threadIdx.x < PBLK) ? g_psum[b * PBLK + threadIdx.x] : 0.0;
    __shared__ double sm[256];
    sm[threadIdx.x] = s;
    __syncthreads();
    for (int st = 128; st > 0; st >>= 1) {
        if (threadIdx.x < st) sm[threadIdx.x] += sm[threadIdx.x + st];
        __syncthreads();
    }
    if (threadIdx.x == 0) out[b] = logdet[b] + (float)sm[0];
}

// ---------------- launch ----------------
extern "C" void kernel_launch(void* const* d_in, const int* in_sizes, int n_in,
                              void* d_out, int out_size)
{
    const float* x    = (const float*)d_in[0];
    const float* ld   = (const float*)d_in[1];
    const float* cond = (const float*)d_in[2];
    const float* w1   = (const float*)d_in[3];
    const float* b1   = (const float*)d_in[4];
    const float* w2   = (const float*)d_in[5];
    const float* b2   = (const float*)d_in[6];
    const float* w3   = (const float*)d_in[7];
    const float* b3   = (const float*)d_in[8];
    float* out = (float*)d_out;

    __half *p_pad1, *p_pad3, *p_h1, *p_w1, *p_w2, *p_w3;
    float *p_params;
    cudaGetSymbolAddress((void**)&p_pad1, g_pad1);
    cudaGetSymbolAddress((void**)&p_pad3, g_pad3);
    cudaGetSymbolAddress((void**)&p_h1, g_h1h);
    cudaGetSymbolAddress((void**)&p_w1, g_w1h);
    cudaGetSymbolAddress((void**)&p_w2, g_w2h);
    cudaGetSymbolAddress((void**)&p_w3, g_w3h);
    cudaGetSymbolAddress((void**)&p_params, g_params);

    // h2 (fp16, 33MB) aliases the head of g_params (144MB): consumed by pad3
    // strictly before conv3 writes params. Safe ordering on one stream.
    __half* p_h2 = reinterpret_cast<__half*>(p_params);

    cudaFuncSetAttribute((const void*)conv_gemm<true,  true,  HID,  16,  4, 160,  true >,
                         cudaFuncAttributeMaxDynamicSharedMemorySize, CONV_SMEM);
    cudaFuncSetAttribute((const void*)conv_gemm<false, true,  HID,  128, 7, 128,  true >,
                         cudaFuncAttributeMaxDynamicSharedMemorySize, CONV_SMEM);
    cudaFuncSetAttribute((const void*)conv_gemm<true,  false, OUTS, 128, 7, 1152, false>,
                         cudaFuncAttributeMaxDynamicSharedMemorySize, CONV_SMEM);

    {
        const int NW = 128*160 + 128*128 + 384*1152;
        prep_weights<<<(NW + 255) / 256, 256>>>(w1, w2, w3);
    }
    {
        const int N = 3 * BB * 16 * 66 * 32;
        pad1_kernel<<<(N + 255) / 256, 256>>>(x, cond);
    }
    conv_gemm<true,  true,  HID, 16,  4, 160, true ><<<dim3(32, 1, BB), 256, CONV_SMEM>>>(p_pad1, p_w1, b1, p_h1);
    conv_gemm<false, true,  HID, 128, 7, 128, true ><<<dim3(32, 1, BB), 256, CONV_SMEM>>>(p_h1,   p_w2, b2, p_h2);
    {
        const int N = 3 * BB * HID * 66 * 32;
        pad3_kernel<<<(N + 255) / 256, 256>>>(p_h2);
    }
    conv_gemm<true,  false, OUTS, 128, 7, 1152, false><<<dim3(32, 3, BB), 256, CONV_SMEM>>>(p_pad3, p_w3, b3, p_params);
    rqs_kernel<<<dim3(PBLK, BB), 256>>>(x, out);
    logdet_reduce<<<BB, 256>>>(ld, out + NTOT);
}